// round 6
// baseline (speedup 1.0000x reference)
#include <cuda_runtime.h>
#include <cuda_bf16.h>
#include <cstdint>

#define NN 50000
#define NE 200000
#define EPSV 1e-5f
#define SLOPE 0.01f
#define NTILES 1563          // ceil(NE/128)
#define EGRID 148
#define BS 80                // smem row stride (bytes) for int8 A/B tiles

// ---- dynamic smem byte offsets ----
#define OFF_BS   0           // B digits [1024 n][64 B + pad]      81920
#define OFF_AS   81920       // A digits [128 e][64 B + pad]       10240
#define OFF_XJ   92160       // xjT [32 i][128 e] float            16384
#define OFF_MSG  108544      // msg [2 Nw][128 e][33] float        33792
#define OFF_B2S  142336      // 1024 float
#define OFF_TNS  146432      // 1024 float (column scales)
#define OFF_W1S  150528      // 512 float
#define OFF_B1S  152576      // 32 float
#define OFF_SE   152704      // 128 float (row scales)
#define OFF_DST  153216      // 128 int
#define SMEM_BYTES 153728

// preprocessed weights
__device__ uint32_t g_Bq[1024 * 16];   // [n][16 words]: w0-7 = G1 k0-31, w8-15 = G2
__device__ float g_tn[1024];
__device__ float g_b2f[1024];
__device__ float g_W1f[512];           // [d][k]
__device__ float g_b1f[32];
__device__ int   g_is64;

// ---------------- helpers ----------------
static __device__ __forceinline__ uint32_t smem_u32(const void* p) {
    uint32_t a;
    asm("{ .reg .u64 t; cvta.to.shared.u64 t, %1; cvt.u32.u64 %0, t; }" : "=r"(a) : "l"(p));
    return a;
}
static __device__ __forceinline__ void ldsm4(uint32_t r[4], uint32_t addr) {
    asm volatile("ldmatrix.sync.aligned.m8n8.x4.shared.b16 {%0,%1,%2,%3}, [%4];"
        : "=r"(r[0]), "=r"(r[1]), "=r"(r[2]), "=r"(r[3]) : "r"(addr));
}
static __device__ __forceinline__ void ldsm2(uint32_t r[2], uint32_t addr) {
    asm volatile("ldmatrix.sync.aligned.m8n8.x2.shared.b16 {%0,%1}, [%2];"
        : "=r"(r[0]), "=r"(r[1]) : "r"(addr));
}
static __device__ __forceinline__ void mma_s8(int c[4], const uint32_t a[4], const uint32_t b[2]) {
    asm volatile("mma.sync.aligned.m16n8k32.row.col.s32.s8.s8.s32 "
        "{%0,%1,%2,%3}, {%4,%5,%6,%7}, {%8,%9}, {%0,%1,%2,%3};"
        : "+r"(c[0]), "+r"(c[1]), "+r"(c[2]), "+r"(c[3])
        : "r"(a[0]), "r"(a[1]), "r"(a[2]), "r"(a[3]), "r"(b[0]), "r"(b[1]));
}
// int -> float for |v| < 2^22, via magic constant (avoids I2F latency/throughput)
static __device__ __forceinline__ float i2f22(int v) {
    return __int_as_float(v + 0x4B400000) - 12582912.0f;
}
static __device__ __forceinline__ uint32_t pack4(int a, int b, int c, int d) {
    return (uint32_t)(a & 0xFF) | ((uint32_t)(b & 0xFF) << 8) |
           ((uint32_t)(c & 0xFF) << 16) | ((uint32_t)d << 24);
}

// ---------------------------------------------------------------------------
// fold: BN into weights; W2f column -> int8 two-digit quantization.
// ---------------------------------------------------------------------------
__global__ void fold_kernel(const float* __restrict__ W1, const float* __restrict__ b1,
                            const float* __restrict__ g1, const float* __restrict__ be1,
                            const float* __restrict__ m1, const float* __restrict__ v1,
                            const float* __restrict__ W2, const float* __restrict__ b2,
                            const float* __restrict__ g2, const float* __restrict__ be2,
                            const float* __restrict__ m2, const float* __restrict__ v2,
                            const int* __restrict__ ei32)
{
    int n = blockIdx.x * blockDim.x + threadIdx.x;   // 0..1023
    if (n >= 1024) return;
    float s = g2[n] * rsqrtf(v2[n] + EPSV);
    float w[32], wmax = 0.f;
    #pragma unroll
    for (int k = 0; k < 32; k++) {
        w[k] = W2[k * 1024 + n] * s;
        wmax = fmaxf(wmax, fabsf(w[k]));
    }
    float inv = wmax > 0.f ? 127.f / wmax : 0.f;
    g_tn[n] = wmax > 0.f ? wmax * (1.f / 127.f) : 0.f;
    int d1[32], d2[32];
    #pragma unroll
    for (int k = 0; k < 32; k++) {
        float q = w[k] * inv;
        int i1 = __float2int_rn(q);
        int i2 = __float2int_rn(256.f * (q - (float)i1));
        d1[k] = i1;
        d2[k] = min(i2, 127);
    }
    #pragma unroll
    for (int j = 0; j < 8; j++) {
        g_Bq[n * 16 + j]     = pack4(d1[4*j], d1[4*j+1], d1[4*j+2], d1[4*j+3]);
        g_Bq[n * 16 + 8 + j] = pack4(d2[4*j], d2[4*j+1], d2[4*j+2], d2[4*j+3]);
    }
    g_b2f[n] = (b2[n] - m2[n]) * s + be2[n];
    if (n < 32) {
        float s1 = g1[n] * rsqrtf(v1[n] + EPSV);
        g_b1f[n] = (b1[n] - m1[n]) * s1 + be1[n];
        #pragma unroll
        for (int d = 0; d < 16; d++)
            g_W1f[d * 32 + n] = W1[d * 32 + n] * s1;
    }
    if (n == 0) {
        int all0 = 1;
        for (int i = 0; i < 64; i++)
            if (ei32[2 * i + 1] != 0) { all0 = 0; break; }
        g_is64 = all0;
    }
}

// ---------------------------------------------------------------------------
// out[n,:] = bias + x[n,:] @ root
// ---------------------------------------------------------------------------
__global__ void init_kernel(const float* __restrict__ x,
                            const float* __restrict__ root,
                            const float* __restrict__ bias,
                            float* __restrict__ out)
{
    __shared__ float root_s[1024];
    __shared__ float bias_s[32];
    int t = threadIdx.x;
    for (int i = t; i < 1024; i += blockDim.x) root_s[i] = root[i];
    if (t < 32) bias_s[t] = bias[t];
    __syncthreads();
    int lane = t & 31, w = t >> 5;
    int n = blockIdx.x * (blockDim.x >> 5) + w;
    if (n >= NN) return;
    float xv = x[n * 32 + lane];
    float acc = bias_s[lane];
    #pragma unroll
    for (int i = 0; i < 32; i++)
        acc = fmaf(__shfl_sync(0xffffffffu, xv, i), root_s[i * 32 + lane], acc);
    out[n * 32 + lane] = acc;
}

// ---------------------------------------------------------------------------
// Persistent fused edge kernel: int8 two-digit mma.sync GEMM + fused epilogue.
// ---------------------------------------------------------------------------
extern __shared__ char smem[];

__global__ void __launch_bounds__(256, 1)
edge_kernel(const float* __restrict__ x,
            const int*   __restrict__ ei32,
            const float* __restrict__ edge_attr,
            float* __restrict__ out)
{
    const int tid = threadIdx.x;
    const int lane = tid & 31, wid = tid >> 5;
    const int Mw = wid & 3, Nw = wid >> 2;
    uint32_t su = smem_u32(smem);

    // ---- persistent copies ----
    {
        const uint4* bs = (const uint4*)g_Bq;
        for (int i = tid; i < 4096; i += 256) {     // 1024 rows x 4 uint4
            int n = i >> 2, seg = i & 3;
            *(uint4*)(smem + OFF_BS + n * BS + seg * 16) = bs[i];
        }
        float* b2w = (float*)(smem + OFF_B2S);
        for (int i = tid; i < 1024; i += 256) b2w[i] = g_b2f[i];
        float* tnw = (float*)(smem + OFF_TNS);
        for (int i = tid; i < 1024; i += 256) tnw[i] = g_tn[i];
        float* w1w = (float*)(smem + OFF_W1S);
        for (int i = tid; i < 512; i += 256) w1w[i] = g_W1f[i];
        if (tid < 32) ((float*)(smem + OFF_B1S))[tid] = g_b1f[tid];
    }
    const int is64 = g_is64;
    __syncthreads();

    // ldmatrix base addresses (b16-view of int8 tiles)
    uint32_t a_base = su + OFF_AS + (uint32_t)(Mw * 32 + (lane & 15)) * BS + ((lane >> 4) * 16);
    uint32_t b_base = su + OFF_BS + (uint32_t)(Nw * 512 + (lane & 7)) * BS + (((lane >> 3) & 1) * 16);

    const float* b2s = (const float*)(smem + OFF_B2S);
    const float* tns = (const float*)(smem + OFF_TNS);
    const float* xj  = (const float*)(smem + OFF_XJ);
    const float* ses = (const float*)(smem + OFF_SE);
    float* ms        = (float*)(smem + OFF_MSG) + Nw * (128 * 33);
    const float* ms0 = (const float*)(smem + OFF_MSG);
    const float* ms1 = ms0 + 128 * 33;
    int* dst_s       = (int*)(smem + OFF_DST);

    for (int tile = blockIdx.x; tile < NTILES; tile += gridDim.x) {
        // ============ phase 1: gather x_j, layer 1, quantize A ============
        {
            int e = tid >> 1, hf = tid & 1;         // thread pair per edge
            int eid = tile * 128 + e;
            int valid = eid < NE;
            int eidc = valid ? eid : NE - 1;
            int src, dd;
            if (is64) { src = ei32[2 * eidc]; dd = ei32[2 * (NE + eidc)]; }
            else      { src = ei32[eidc];     dd = ei32[NE + eidc]; }
            if (hf == 0) dst_s[e] = valid ? dd : -1;

            // gather x[src] -> xjT[i][e]
            float* xjw = (float*)(smem + OFF_XJ);
            const float4* xr = (const float4*)(x + (size_t)src * 32) + hf * 4;
            #pragma unroll
            for (int q = 0; q < 4; q++) {
                float4 v = xr[q];
                int i0 = hf * 16 + q * 4;
                xjw[(i0 + 0) * 128 + e] = v.x;
                xjw[(i0 + 1) * 128 + e] = v.y;
                xjw[(i0 + 2) * 128 + e] = v.z;
                xjw[(i0 + 3) * 128 + e] = v.w;
            }

            // layer 1: h = leaky(ea @ W1f + b1f) (both halves compute full h)
            float hval[32];
            {
                const float* W1s = (const float*)(smem + OFF_W1S);
                const float* b1s = (const float*)(smem + OFF_B1S);
                #pragma unroll
                for (int k = 0; k < 32; k++) hval[k] = b1s[k];
                const float4* er = (const float4*)(edge_attr + (size_t)eidc * 16);
                #pragma unroll
                for (int qq = 0; qq < 4; qq++) {
                    float4 q = er[qq];
                    float ev[4] = {q.x, q.y, q.z, q.w};
                    #pragma unroll
                    for (int dj = 0; dj < 4; dj++) {
                        int d = qq * 4 + dj;
                        #pragma unroll
                        for (int k = 0; k < 32; k++)
                            hval[k] = fmaf(ev[dj], W1s[d * 32 + k], hval[k]);
                    }
                }
                #pragma unroll
                for (int k = 0; k < 32; k++) hval[k] = fmaxf(hval[k], SLOPE * hval[k]);
            }

            // quantize: se = hmax/127; H1 = rn(h/se); H2 = rn(256(h/se - H1))
            float hmax = 0.f;
            #pragma unroll
            for (int k = 0; k < 32; k++) hmax = fmaxf(hmax, fabsf(hval[k]));
            float inv = hmax > 0.f ? 127.f / hmax : 0.f;
            if (hf == 0) ((float*)(smem + OFF_SE))[e] = hmax > 0.f ? hmax * (1.f / 127.f) : 0.f;

            uint32_t wds[8];
            if (hf == 0) {
                #pragma unroll
                for (int j = 0; j < 8; j++) {
                    int i0 = __float2int_rn(hval[4*j]   * inv);
                    int i1 = __float2int_rn(hval[4*j+1] * inv);
                    int i2 = __float2int_rn(hval[4*j+2] * inv);
                    int i3 = __float2int_rn(hval[4*j+3] * inv);
                    wds[j] = pack4(i0, i1, i2, i3);
                }
            } else {
                #pragma unroll
                for (int j = 0; j < 8; j++) {
                    int v[4];
                    #pragma unroll
                    for (int c = 0; c < 4; c++) {
                        float q = hval[4*j+c] * inv;
                        int a = __float2int_rn(q);
                        v[c] = min(__float2int_rn(256.f * (q - (float)a)), 127);
                    }
                    wds[j] = pack4(v[0], v[1], v[2], v[3]);
                }
            }
            char* arow = smem + OFF_AS + e * BS + hf * 32;
            *(uint4*)(arow)      = make_uint4(wds[0], wds[1], wds[2], wds[3]);
            *(uint4*)(arow + 16) = make_uint4(wds[4], wds[5], wds[6], wds[7]);
        }
        __syncthreads();

        // ============ phase 2: int8 MMA + fused epilogue ============
        uint32_t h1f[2][4], h2f[2][4];
        #pragma unroll
        for (int c = 0; c < 2; c++) {
            ldsm4(h1f[c], a_base + c * (16 * BS));
            ldsm4(h2f[c], a_base + c * (16 * BS) + 32);
        }
        const int r0 = Mw * 32 + (lane >> 2);
        float se0 = ses[r0], se1 = ses[r0 + 8], se2 = ses[r0 + 16], se3 = ses[r0 + 24];

        float msg[2][2][4][2];
        #pragma unroll
        for (int a1 = 0; a1 < 2; a1++)
            #pragma unroll
            for (int a2 = 0; a2 < 2; a2++)
                #pragma unroll
                for (int a3 = 0; a3 < 4; a3++)
                    { msg[a1][a2][a3][0] = 0.f; msg[a1][a2][a3][1] = 0.f; }

        #pragma unroll 4
        for (int nb = 0; nb < 64; nb++) {
            uint32_t ba = b_base + (uint32_t)nb * (8 * BS);
            uint32_t gd1[2], gd2[2];
            ldsm2(gd1, ba);
            ldsm2(gd2, ba + 32);

            int ca0[4] = {0,0,0,0}, cb0[4] = {0,0,0,0};
            int ca1[4] = {0,0,0,0}, cb1[4] = {0,0,0,0};
            mma_s8(ca0, h1f[0], gd1);
            mma_s8(ca1, h1f[1], gd1);
            mma_s8(cb0, h1f[0], gd2);
            mma_s8(cb1, h1f[1], gd2);
            mma_s8(cb0, h2f[0], gd1);
            mma_s8(cb1, h2f[1], gd1);

            int n0 = Nw * 512 + nb * 8;
            float2 b2v = *(const float2*)(b2s + n0 + (lane & 3) * 2);
            float2 tnv = *(const float2*)(tns + n0 + (lane & 3) * 2);
            int ii = n0 >> 5;
            int nbq = nb & 3;
            float xv00 = xj[ii * 128 + r0];
            float xv01 = xj[ii * 128 + r0 + 8];
            float xv10 = xj[ii * 128 + r0 + 16];
            float xv11 = xj[ii * 128 + r0 + 24];

            float t, v;
            t = fmaf(i2f22(cb0[0]), 0.00390625f, i2f22(ca0[0]));
            v = fmaf(t, se0 * tnv.x, b2v.x); v = fmaxf(v, SLOPE * v);
            msg[0][0][nbq][0] = fmaf(xv00, v, msg[0][0][nbq][0]);
            t = fmaf(i2f22(cb0[1]), 0.00390625f, i2f22(ca0[1]));
            v = fmaf(t, se0 * tnv.y, b2v.y); v = fmaxf(v, SLOPE * v);
            msg[0][0][nbq][1] = fmaf(xv00, v, msg[0][0][nbq][1]);
            t = fmaf(i2f22(cb0[2]), 0.00390625f, i2f22(ca0[2]));
            v = fmaf(t, se1 * tnv.x, b2v.x); v = fmaxf(v, SLOPE * v);
            msg[0][1][nbq][0] = fmaf(xv01, v, msg[0][1][nbq][0]);
            t = fmaf(i2f22(cb0[3]), 0.00390625f, i2f22(ca0[3]));
            v = fmaf(t, se1 * tnv.y, b2v.y); v = fmaxf(v, SLOPE * v);
            msg[0][1][nbq][1] = fmaf(xv01, v, msg[0][1][nbq][1]);
            t = fmaf(i2f22(cb1[0]), 0.00390625f, i2f22(ca1[0]));
            v = fmaf(t, se2 * tnv.x, b2v.x); v = fmaxf(v, SLOPE * v);
            msg[1][0][nbq][0] = fmaf(xv10, v, msg[1][0][nbq][0]);
            t = fmaf(i2f22(cb1[1]), 0.00390625f, i2f22(ca1[1]));
            v = fmaf(t, se2 * tnv.y, b2v.y); v = fmaxf(v, SLOPE * v);
            msg[1][0][nbq][1] = fmaf(xv10, v, msg[1][0][nbq][1]);
            t = fmaf(i2f22(cb1[2]), 0.00390625f, i2f22(ca1[2]));
            v = fmaf(t, se3 * tnv.x, b2v.x); v = fmaxf(v, SLOPE * v);
            msg[1][1][nbq][0] = fmaf(xv11, v, msg[1][1][nbq][0]);
            t = fmaf(i2f22(cb1[3]), 0.00390625f, i2f22(ca1[3]));
            v = fmaf(t, se3 * tnv.y, b2v.y); v = fmaxf(v, SLOPE * v);
            msg[1][1][nbq][1] = fmaf(xv11, v, msg[1][1][nbq][1]);
        }

        // ============ phase 3: msg -> smem, sum halves, coalesced atomics ============
        #pragma unroll
        for (int ch = 0; ch < 2; ch++)
            #pragma unroll
            for (int rh = 0; rh < 2; rh++)
                #pragma unroll
                for (int j = 0; j < 4; j++)
                    #pragma unroll
                    for (int d = 0; d < 2; d++) {
                        int row = Mw * 32 + ch * 16 + rh * 8 + (lane >> 2);
                        int o = (lane & 3) * 2 + 8 * j + d;
                        ms[row * 33 + o] = msg[ch][rh][j][d];
                    }
        __syncthreads();

        #pragma unroll 1
        for (int ee = 0; ee < 16; ee++) {
            int e2 = wid * 16 + ee;
            int dd = dst_s[e2];
            if (dd >= 0)
                atomicAdd(out + (size_t)dd * 32 + lane,
                          ms0[e2 * 33 + lane] + ms1[e2 * 33 + lane]);
        }
        __syncthreads();
    }
}

// ---------------------------------------------------------------------------
extern "C" void kernel_launch(void* const* d_in, const int* in_sizes, int n_in,
                              void* d_out, int out_size)
{
    const float* x    = (const float*)d_in[0];
    const int*   ei   = (const int*)d_in[1];
    const float* ea   = (const float*)d_in[2];
    const float* W1   = (const float*)d_in[4];
    const float* b1   = (const float*)d_in[5];
    const float* g1   = (const float*)d_in[6];
    const float* be1  = (const float*)d_in[7];
    const float* m1   = (const float*)d_in[8];
    const float* v1   = (const float*)d_in[9];
    const float* W2   = (const float*)d_in[10];
    const float* b2   = (const float*)d_in[11];
    const float* g2   = (const float*)d_in[12];
    const float* be2  = (const float*)d_in[13];
    const float* m2   = (const float*)d_in[14];
    const float* v2   = (const float*)d_in[15];
    const float* root = (const float*)d_in[16];
    const float* bias = (const float*)d_in[17];
    float* out = (float*)d_out;

    cudaFuncSetAttribute(edge_kernel, cudaFuncAttributeMaxDynamicSharedMemorySize, SMEM_BYTES);

    fold_kernel<<<4, 256>>>(W1, b1, g1, be1, m1, v1, W2, b2, g2, be2, m2, v2, ei);
    init_kernel<<<(NN + 7) / 8, 256>>>(x, root, bias, out);
    edge_kernel<<<EGRID, 256, SMEM_BYTES>>>(x, ei, ea, out);
}

// round 7
// speedup vs baseline: 2.4461x; 2.4461x over previous
#include <cuda_runtime.h>
#include <cuda_fp16.h>
#include <cstdint>

#define NN 50000
#define NE 200000
#define EPSV 1e-5f
#define SLOPE 0.01f
#define NTILES 1563          // ceil(NE/128)
#define EGRID 148

#define BSTRIDE 144          // B tile row stride (128B data + 16 pad)
#define ASTRIDE 80           // A tile row stride (64B data + 16 pad)
#define INV1024 9.765625e-4f

// ---- dynamic smem byte offsets ----
#define OFF_BS   0           // B [1024 n][64 fp16: hi k0-31 | lo*1024 k0-31]  147456
#define OFF_AS   147456      // A [128 e][32 fp16]                              10240
#define OFF_XJ   157696      // xjT [32 i][128 e] float                         16384
#define OFF_MSG  174080      // msg [2 Nw][128 e][33] float                     33792
#define OFF_B2S  207872      // 1024 float
#define OFF_W1S  211968      // 512 float
#define OFF_B1S  214016      // 32 float
#define OFF_DST  214144      // 128 int
#define SMEM_BYTES 214656

// preprocessed weights
__device__ __half g_Bh[1024 * 64];   // [n][k]: k0-31 = fp16(W2f), k32-63 = fp16((W2f-hi)*1024)
__device__ float g_b2f[1024];
__device__ float g_W1f[512];         // [d][k]
__device__ float g_b1f[32];
__device__ int   g_is64;

// ---------------- helpers ----------------
static __device__ __forceinline__ uint32_t smem_u32(const void* p) {
    uint32_t a;
    asm("{ .reg .u64 t; cvta.to.shared.u64 t, %1; cvt.u32.u64 %0, t; }" : "=r"(a) : "l"(p));
    return a;
}
static __device__ __forceinline__ void ldsm4(uint32_t r[4], uint32_t addr) {
    asm volatile("ldmatrix.sync.aligned.m8n8.x4.shared.b16 {%0,%1,%2,%3}, [%4];"
        : "=r"(r[0]), "=r"(r[1]), "=r"(r[2]), "=r"(r[3]) : "r"(addr));
}
static __device__ __forceinline__ void ldsm2(uint32_t r[2], uint32_t addr) {
    asm volatile("ldmatrix.sync.aligned.m8n8.x2.shared.b16 {%0,%1}, [%2];"
        : "=r"(r[0]), "=r"(r[1]) : "r"(addr));
}
static __device__ __forceinline__ void mma_f16(float c[4], const uint32_t a[4], const uint32_t b[2]) {
    asm volatile("mma.sync.aligned.m16n8k16.row.col.f32.f16.f16.f32 "
        "{%0,%1,%2,%3}, {%4,%5,%6,%7}, {%8,%9}, {%0,%1,%2,%3};"
        : "+f"(c[0]), "+f"(c[1]), "+f"(c[2]), "+f"(c[3])
        : "r"(a[0]), "r"(a[1]), "r"(a[2]), "r"(a[3]), "r"(b[0]), "r"(b[1]));
}

// ---------------------------------------------------------------------------
// fold: BN into weights; W2f -> fp16 two-term split (lo scaled x1024).
// ---------------------------------------------------------------------------
__global__ void fold_kernel(const float* __restrict__ W1, const float* __restrict__ b1,
                            const float* __restrict__ g1, const float* __restrict__ be1,
                            const float* __restrict__ m1, const float* __restrict__ v1,
                            const float* __restrict__ W2, const float* __restrict__ b2,
                            const float* __restrict__ g2, const float* __restrict__ be2,
                            const float* __restrict__ m2, const float* __restrict__ v2,
                            const int* __restrict__ ei32)
{
    int idx = blockIdx.x * blockDim.x + threadIdx.x;   // 0..32767
    if (idx >= 32768) return;
    int n = idx & 1023;
    int k = idx >> 10;                                 // 0..31
    float s = g2[n] * rsqrtf(v2[n] + EPSV);
    float w = W2[k * 1024 + n] * s;
    __half hi = __float2half_rn(w);
    __half lo = __float2half_rn((w - __half2float(hi)) * 1024.f);
    g_Bh[n * 64 + k]      = hi;
    g_Bh[n * 64 + 32 + k] = lo;
    if (k == 0) {
        g_b2f[n] = (b2[n] - m2[n]) * s + be2[n];
        if (n < 32) {
            float s1 = g1[n] * rsqrtf(v1[n] + EPSV);
            g_b1f[n] = (b1[n] - m1[n]) * s1 + be1[n];
            #pragma unroll
            for (int d = 0; d < 16; d++)
                g_W1f[d * 32 + n] = W1[d * 32 + n] * s1;
        }
        if (n == 0) {
            int all0 = 1;
            for (int i = 0; i < 64; i++)
                if (ei32[2 * i + 1] != 0) { all0 = 0; break; }
            g_is64 = all0;
        }
    }
}

// ---------------------------------------------------------------------------
// out[n,:] = bias + x[n,:] @ root
// ---------------------------------------------------------------------------
__global__ void init_kernel(const float* __restrict__ x,
                            const float* __restrict__ root,
                            const float* __restrict__ bias,
                            float* __restrict__ out)
{
    __shared__ float root_s[1024];
    __shared__ float bias_s[32];
    int t = threadIdx.x;
    for (int i = t; i < 1024; i += blockDim.x) root_s[i] = root[i];
    if (t < 32) bias_s[t] = bias[t];
    __syncthreads();
    int lane = t & 31, w = t >> 5;
    int n = blockIdx.x * (blockDim.x >> 5) + w;
    if (n >= NN) return;
    float xv = x[n * 32 + lane];
    float acc = bias_s[lane];
    #pragma unroll
    for (int i = 0; i < 32; i++)
        acc = fmaf(__shfl_sync(0xffffffffu, xv, i), root_s[i * 32 + lane], acc);
    out[n * 32 + lane] = acc;
}

// ---------------------------------------------------------------------------
// Persistent fused edge kernel: fp16 2-term mma.sync GEMM + fused epilogue.
// ---------------------------------------------------------------------------
extern __shared__ char smem[];

__global__ void __launch_bounds__(256, 1)
edge_kernel(const float* __restrict__ x,
            const int*   __restrict__ ei32,
            const float* __restrict__ edge_attr,
            float* __restrict__ out)
{
    const int tid = threadIdx.x;
    const int lane = tid & 31, wid = tid >> 5;
    const int Mw = wid & 3, Nw = wid >> 2;
    uint32_t su = smem_u32(smem);

    // ---- persistent copies: B, b2f, W1f, b1f ----
    {
        const int4* bs = (const int4*)g_Bh;
        for (int i = tid; i < 8192; i += 256) {        // 1024 rows x 8 int4
            int n = i >> 3, seg = i & 7;
            *(int4*)(smem + OFF_BS + n * BSTRIDE + seg * 16) = bs[i];
        }
        float* b2w = (float*)(smem + OFF_B2S);
        for (int i = tid; i < 1024; i += 256) b2w[i] = g_b2f[i];
        float* w1w = (float*)(smem + OFF_W1S);
        for (int i = tid; i < 512; i += 256) w1w[i] = g_W1f[i];
        if (tid < 32) ((float*)(smem + OFF_B1S))[tid] = g_b1f[tid];
    }
    const int is64 = g_is64;
    __syncthreads();

    // ldmatrix base addresses
    uint32_t a_base = su + OFF_AS + (uint32_t)(Mw * 32 + (lane & 15)) * ASTRIDE + (lane >> 4) * 16;
    uint32_t b_base = su + OFF_BS + (uint32_t)(Nw * 512 + (lane & 7)) * BSTRIDE + (((lane >> 3) & 1) * 8) * 2;

    const float* b2s = (const float*)(smem + OFF_B2S);
    const float* xj  = (const float*)(smem + OFF_XJ);
    float* ms        = (float*)(smem + OFF_MSG) + Nw * (128 * 33);
    const float* ms0 = (const float*)(smem + OFF_MSG);
    const float* ms1 = ms0 + 128 * 33;
    int* dst_s       = (int*)(smem + OFF_DST);

    for (int tile = blockIdx.x; tile < NTILES; tile += gridDim.x) {
        // ============ phase 1: gather x_j, layer 1, A-tile build ============
        {
            int e = tid >> 1, hf = tid & 1;         // thread pair per edge
            int eid = tile * 128 + e;
            int valid = eid < NE;
            int eidc = valid ? eid : NE - 1;
            int src, dd;
            if (is64) { src = ei32[2 * eidc]; dd = ei32[2 * (NE + eidc)]; }
            else      { src = ei32[eidc];     dd = ei32[NE + eidc]; }
            if (hf == 0) dst_s[e] = valid ? dd : -1;

            // gather x[src] -> xjT[i][e], each half does 16 i's
            float* xjw = (float*)(smem + OFF_XJ);
            const float4* xr = (const float4*)(x + (size_t)src * 32) + hf * 4;
            #pragma unroll
            for (int q = 0; q < 4; q++) {
                float4 v = xr[q];
                int i0 = hf * 16 + q * 4;
                xjw[(i0 + 0) * 128 + e] = v.x;
                xjw[(i0 + 1) * 128 + e] = v.y;
                xjw[(i0 + 2) * 128 + e] = v.z;
                xjw[(i0 + 3) * 128 + e] = v.w;
            }

            // layer 1: h = leaky(ea @ W1f + b1f) (both halves compute full h)
            float hval[32];
            {
                const float* W1s = (const float*)(smem + OFF_W1S);
                const float* b1s = (const float*)(smem + OFF_B1S);
                #pragma unroll
                for (int k = 0; k < 32; k++) hval[k] = b1s[k];
                const float4* er = (const float4*)(edge_attr + (size_t)eidc * 16);
                #pragma unroll
                for (int qq = 0; qq < 4; qq++) {
                    float4 q = er[qq];
                    float ev[4] = {q.x, q.y, q.z, q.w};
                    #pragma unroll
                    for (int dj = 0; dj < 4; dj++) {
                        int d = qq * 4 + dj;
                        #pragma unroll
                        for (int k = 0; k < 32; k++)
                            hval[k] = fmaf(ev[dj], W1s[d * 32 + k], hval[k]);
                    }
                }
                #pragma unroll
                for (int k = 0; k < 32; k++) hval[k] = fmaxf(hval[k], SLOPE * hval[k]);
            }

            // A row: fp16(h); half hf writes k = hf*16 .. hf*16+15  (32 bytes)
            union { __half2 h2[8]; uint4 u4[2]; } pk;
            #pragma unroll
            for (int j = 0; j < 8; j++) {
                int k = hf * 16 + 2 * j;
                pk.h2[j] = __halves2half2(__float2half_rn(hval[k]),
                                          __float2half_rn(hval[k + 1]));
            }
            char* arow = smem + OFF_AS + e * ASTRIDE + hf * 32;
            *(uint4*)(arow)      = pk.u4[0];
            *(uint4*)(arow + 16) = pk.u4[1];
        }
        __syncthreads();

        // ============ phase 2: fp16 MMA + fused epilogue ============
        // af[chunk][khalf]: A frags for rows Mw*32 + chunk*16, k = khalf*16..+15
        uint32_t af[2][2][4];
        #pragma unroll
        for (int c = 0; c < 2; c++) {
            ldsm4(af[c][0], a_base + c * (16 * ASTRIDE));
            ldsm4(af[c][1], a_base + c * (16 * ASTRIDE) + 32);
        }
        const int r0 = Mw * 32 + (lane >> 2);

        float msg[2][2][4][2];
        #pragma unroll
        for (int a1 = 0; a1 < 2; a1++)
            #pragma unroll
            for (int a2 = 0; a2 < 2; a2++)
                #pragma unroll
                for (int a3 = 0; a3 < 4; a3++)
                    { msg[a1][a2][a3][0] = 0.f; msg[a1][a2][a3][1] = 0.f; }

        for (int nbo = 0; nbo < 64; nbo += 4) {
            #pragma unroll
            for (int nbq = 0; nbq < 4; nbq++) {
                int nb = nbo + nbq;
                int n0 = Nw * 512 + nb * 8;
                uint32_t ba = b_base + (uint32_t)(nb * 8) * BSTRIDE;
                uint32_t g0[2], g1[2], g2[2], g3[2];
                ldsm2(g0, ba);         // W_hi k0-15
                ldsm2(g1, ba + 32);    // W_hi k16-31
                ldsm2(g2, ba + 64);    // W_lo*1024 k0-15
                ldsm2(g3, ba + 96);    // W_lo*1024 k16-31
                float2 b2v = *(const float2*)(b2s + n0 + (lane & 3) * 2);
                int ii = n0 >> 5;

                float c0h[4] = {0.f,0.f,0.f,0.f}, c0l[4] = {0.f,0.f,0.f,0.f};
                float c1h[4] = {0.f,0.f,0.f,0.f}, c1l[4] = {0.f,0.f,0.f,0.f};
                mma_f16(c0h, af[0][0], g0);  mma_f16(c1h, af[1][0], g0);
                mma_f16(c0h, af[0][1], g1);  mma_f16(c1h, af[1][1], g1);
                mma_f16(c0l, af[0][0], g2);  mma_f16(c1l, af[1][0], g2);
                mma_f16(c0l, af[0][1], g3);  mma_f16(c1l, af[1][1], g3);

                float xv00 = xj[ii * 128 + r0];
                float xv01 = xj[ii * 128 + r0 + 8];
                float xv10 = xj[ii * 128 + r0 + 16];
                float xv11 = xj[ii * 128 + r0 + 24];
                float v;
                v = fmaf(c0l[0], INV1024, c0h[0]) + b2v.x; v = fmaxf(v, SLOPE * v);
                msg[0][0][nbq][0] = fmaf(xv00, v, msg[0][0][nbq][0]);
                v = fmaf(c0l[1], INV1024, c0h[1]) + b2v.y; v = fmaxf(v, SLOPE * v);
                msg[0][0][nbq][1] = fmaf(xv00, v, msg[0][0][nbq][1]);
                v = fmaf(c0l[2], INV1024, c0h[2]) + b2v.x; v = fmaxf(v, SLOPE * v);
                msg[0][1][nbq][0] = fmaf(xv01, v, msg[0][1][nbq][0]);
                v = fmaf(c0l[3], INV1024, c0h[3]) + b2v.y; v = fmaxf(v, SLOPE * v);
                msg[0][1][nbq][1] = fmaf(xv01, v, msg[0][1][nbq][1]);
                v = fmaf(c1l[0], INV1024, c1h[0]) + b2v.x; v = fmaxf(v, SLOPE * v);
                msg[1][0][nbq][0] = fmaf(xv10, v, msg[1][0][nbq][0]);
                v = fmaf(c1l[1], INV1024, c1h[1]) + b2v.y; v = fmaxf(v, SLOPE * v);
                msg[1][0][nbq][1] = fmaf(xv10, v, msg[1][0][nbq][1]);
                v = fmaf(c1l[2], INV1024, c1h[2]) + b2v.x; v = fmaxf(v, SLOPE * v);
                msg[1][1][nbq][0] = fmaf(xv11, v, msg[1][1][nbq][0]);
                v = fmaf(c1l[3], INV1024, c1h[3]) + b2v.y; v = fmaxf(v, SLOPE * v);
                msg[1][1][nbq][1] = fmaf(xv11, v, msg[1][1][nbq][1]);
            }
        }

        // ============ phase 3: msg -> smem, sum halves, coalesced atomics ============
        #pragma unroll
        for (int ch = 0; ch < 2; ch++)
            #pragma unroll
            for (int rh = 0; rh < 2; rh++)
                #pragma unroll
                for (int j = 0; j < 4; j++)
                    #pragma unroll
                    for (int d = 0; d < 2; d++) {
                        int row = Mw * 32 + ch * 16 + rh * 8 + (lane >> 2);
                        int o = (lane & 3) * 2 + 8 * j + d;
                        ms[row * 33 + o] = msg[ch][rh][j][d];
                    }
        __syncthreads();

        #pragma unroll 1
        for (int ee = 0; ee < 16; ee++) {
            int e2 = wid * 16 + ee;
            int dd = dst_s[e2];
            if (dd >= 0)
                atomicAdd(out + (size_t)dd * 32 + lane,
                          ms0[e2 * 33 + lane] + ms1[e2 * 33 + lane]);
        }
        __syncthreads();   // protect dst_s/xj/A before next tile's writes
    }
}

// ---------------------------------------------------------------------------
extern "C" void kernel_launch(void* const* d_in, const int* in_sizes, int n_in,
                              void* d_out, int out_size)
{
    const float* x    = (const float*)d_in[0];
    const int*   ei   = (const int*)d_in[1];
    const float* ea   = (const float*)d_in[2];
    const float* W1   = (const float*)d_in[4];
    const float* b1   = (const float*)d_in[5];
    const float* g1   = (const float*)d_in[6];
    const float* be1  = (const float*)d_in[7];
    const float* m1   = (const float*)d_in[8];
    const float* v1   = (const float*)d_in[9];
    const float* W2   = (const float*)d_in[10];
    const float* b2   = (const float*)d_in[11];
    const float* g2   = (const float*)d_in[12];
    const float* be2  = (const float*)d_in[13];
    const float* m2   = (const float*)d_in[14];
    const float* v2   = (const float*)d_in[15];
    const float* root = (const float*)d_in[16];
    const float* bias = (const float*)d_in[17];
    float* out = (float*)d_out;

    cudaFuncSetAttribute(edge_kernel, cudaFuncAttributeMaxDynamicSharedMemorySize, SMEM_BYTES);

    fold_kernel<<<128, 256>>>(W1, b1, g1, be1, m1, v1, W2, b2, g2, be2, m2, v2, ei);
    init_kernel<<<(NN + 7) / 8, 256>>>(x, root, bias, out);
    edge_kernel<<<EGRID, 256, SMEM_BYTES>>>(x, ei, ea, out);
}

// round 8
// speedup vs baseline: 3.4154x; 1.3963x over previous
#include <cuda_runtime.h>
#include <cuda_fp16.h>
#include <cstdint>

#define NN 50000
#define NE 200000
#define EPSV 1e-5f
#define SLOPE 0.01f
#define NTILES 1563          // ceil(NE/128)
#define EGRID 148

#define BSTRIDE 80           // B tile row stride (64B data + 16 pad)
#define ASTRIDE 80           // A tile row stride (64B data + 16 pad)

// ---- dynamic smem byte offsets ----
#define OFF_BS   0           // B [1024 n][32 fp16]                 81920
#define OFF_AS   81920       // A [128 e][32 fp16]                  10240
#define OFF_XJ   92160       // xjT [32 i][128 e] float             16384
#define OFF_MSG  108544      // msg [2 Nw][128 e][33] float         33792
#define OFF_B2S  142336      // 1024 float
#define OFF_W1S  146432      // 512 float
#define OFF_B1S  148480      // 32 float
#define OFF_DST  148608      // 128 int
#define SMEM_BYTES 149120

// preprocessed weights
__device__ __half g_Bh[1024 * 32];   // [n][k] fp16(W2f[k][n] * bn-scale)
__device__ float g_b2f[1024];
__device__ float g_W1f[512];         // [d][k]
__device__ float g_b1f[32];
__device__ int   g_is64;

// ---------------- helpers ----------------
static __device__ __forceinline__ uint32_t smem_u32(const void* p) {
    uint32_t a;
    asm("{ .reg .u64 t; cvta.to.shared.u64 t, %1; cvt.u32.u64 %0, t; }" : "=r"(a) : "l"(p));
    return a;
}
static __device__ __forceinline__ void ldsm4(uint32_t r[4], uint32_t addr) {
    asm volatile("ldmatrix.sync.aligned.m8n8.x4.shared.b16 {%0,%1,%2,%3}, [%4];"
        : "=r"(r[0]), "=r"(r[1]), "=r"(r[2]), "=r"(r[3]) : "r"(addr));
}
static __device__ __forceinline__ void ldsm2(uint32_t r[2], uint32_t addr) {
    asm volatile("ldmatrix.sync.aligned.m8n8.x2.shared.b16 {%0,%1}, [%2];"
        : "=r"(r[0]), "=r"(r[1]) : "r"(addr));
}
static __device__ __forceinline__ void mma_f16(float c[4], const uint32_t a[4], const uint32_t b[2]) {
    asm volatile("mma.sync.aligned.m16n8k16.row.col.f32.f16.f16.f32 "
        "{%0,%1,%2,%3}, {%4,%5,%6,%7}, {%8,%9}, {%0,%1,%2,%3};"
        : "+f"(c[0]), "+f"(c[1]), "+f"(c[2]), "+f"(c[3])
        : "r"(a[0]), "r"(a[1]), "r"(a[2]), "r"(a[3]), "r"(b[0]), "r"(b[1]));
}

// ---------------------------------------------------------------------------
// fold: BN into weights; W2f -> single fp16.
// ---------------------------------------------------------------------------
__global__ void fold_kernel(const float* __restrict__ W1, const float* __restrict__ b1,
                            const float* __restrict__ g1, const float* __restrict__ be1,
                            const float* __restrict__ m1, const float* __restrict__ v1,
                            const float* __restrict__ W2, const float* __restrict__ b2,
                            const float* __restrict__ g2, const float* __restrict__ be2,
                            const float* __restrict__ m2, const float* __restrict__ v2,
                            const int* __restrict__ ei32)
{
    int idx = blockIdx.x * blockDim.x + threadIdx.x;   // 0..32767
    if (idx >= 32768) return;
    int n = idx & 1023;
    int k = idx >> 10;                                 // 0..31
    float s = g2[n] * rsqrtf(v2[n] + EPSV);
    g_Bh[n * 32 + k] = __float2half_rn(W2[k * 1024 + n] * s);
    if (k == 0) {
        g_b2f[n] = (b2[n] - m2[n]) * s + be2[n];
        if (n < 32) {
            float s1 = g1[n] * rsqrtf(v1[n] + EPSV);
            g_b1f[n] = (b1[n] - m1[n]) * s1 + be1[n];
            #pragma unroll
            for (int d = 0; d < 16; d++)
                g_W1f[d * 32 + n] = W1[d * 32 + n] * s1;
        }
        if (n == 0) {
            int all0 = 1;
            for (int i = 0; i < 64; i++)
                if (ei32[2 * i + 1] != 0) { all0 = 0; break; }
            g_is64 = all0;
        }
    }
}

// ---------------------------------------------------------------------------
// out[n,:] = bias + x[n,:] @ root
// ---------------------------------------------------------------------------
__global__ void init_kernel(const float* __restrict__ x,
                            const float* __restrict__ root,
                            const float* __restrict__ bias,
                            float* __restrict__ out)
{
    __shared__ float root_s[1024];
    __shared__ float bias_s[32];
    int t = threadIdx.x;
    for (int i = t; i < 1024; i += blockDim.x) root_s[i] = root[i];
    if (t < 32) bias_s[t] = bias[t];
    __syncthreads();
    int lane = t & 31, w = t >> 5;
    int n = blockIdx.x * (blockDim.x >> 5) + w;
    if (n >= NN) return;
    float xv = x[n * 32 + lane];
    float acc = bias_s[lane];
    #pragma unroll
    for (int i = 0; i < 32; i++)
        acc = fmaf(__shfl_sync(0xffffffffu, xv, i), root_s[i * 32 + lane], acc);
    out[n * 32 + lane] = acc;
}

// ---------------------------------------------------------------------------
// Persistent fused edge kernel: single-fp16 mma.sync GEMM + fused epilogue.
// ---------------------------------------------------------------------------
extern __shared__ char smem[];

__global__ void __launch_bounds__(256, 1)
edge_kernel(const float* __restrict__ x,
            const int*   __restrict__ ei32,
            const float* __restrict__ edge_attr,
            float* __restrict__ out)
{
    const int tid = threadIdx.x;
    const int lane = tid & 31, wid = tid >> 5;
    const int Mw = wid & 3, Nw = wid >> 2;
    uint32_t su = smem_u32(smem);

    // ---- persistent copies: B, b2f, W1f, b1f ----
    {
        const int4* bs = (const int4*)g_Bh;
        for (int i = tid; i < 4096; i += 256) {        // 1024 rows x 4 int4
            int n = i >> 2, seg = i & 3;
            *(int4*)(smem + OFF_BS + n * BSTRIDE + seg * 16) = bs[i];
        }
        float* b2w = (float*)(smem + OFF_B2S);
        for (int i = tid; i < 1024; i += 256) b2w[i] = g_b2f[i];
        float* w1w = (float*)(smem + OFF_W1S);
        for (int i = tid; i < 512; i += 256) w1w[i] = g_W1f[i];
        if (tid < 32) ((float*)(smem + OFF_B1S))[tid] = g_b1f[tid];
    }
    const int is64 = g_is64;
    __syncthreads();

    // ldmatrix base addresses
    uint32_t a_base = su + OFF_AS + (uint32_t)(Mw * 32 + (lane & 15)) * ASTRIDE + (lane >> 4) * 16;
    uint32_t b_base = su + OFF_BS + (uint32_t)(Nw * 512 + (lane & 7)) * BSTRIDE + ((lane >> 3) & 1) * 16;

    const float* b2s = (const float*)(smem + OFF_B2S);
    const float* xj  = (const float*)(smem + OFF_XJ);
    float* ms        = (float*)(smem + OFF_MSG) + Nw * (128 * 33);
    const float* ms0 = (const float*)(smem + OFF_MSG);
    const float* ms1 = ms0 + 128 * 33;
    int* dst_s       = (int*)(smem + OFF_DST);

    for (int tile = blockIdx.x; tile < NTILES; tile += gridDim.x) {
        // ============ phase 1: gather x_j, layer 1 (half h each), A-tile ============
        {
            int e = tid >> 1, hf = tid & 1;         // thread pair per edge
            int eid = tile * 128 + e;
            int valid = eid < NE;
            int eidc = valid ? eid : NE - 1;
            int src, dd;
            if (is64) { src = ei32[2 * eidc]; dd = ei32[2 * (NE + eidc)]; }
            else      { src = ei32[eidc];     dd = ei32[NE + eidc]; }
            if (hf == 0) dst_s[e] = valid ? dd : -1;

            // gather x[src] -> xjT[i][e], each half does 16 i's
            float* xjw = (float*)(smem + OFF_XJ);
            const float4* xr = (const float4*)(x + (size_t)src * 32) + hf * 4;
            #pragma unroll
            for (int q = 0; q < 4; q++) {
                float4 v = xr[q];
                int i0 = hf * 16 + q * 4;
                xjw[(i0 + 0) * 128 + e] = v.x;
                xjw[(i0 + 1) * 128 + e] = v.y;
                xjw[(i0 + 2) * 128 + e] = v.z;
                xjw[(i0 + 3) * 128 + e] = v.w;
            }

            // layer 1: each half computes only its own k-range [hf*16, hf*16+16)
            float hval[16];
            {
                const float* W1s = (const float*)(smem + OFF_W1S) + hf * 16;
                const float* b1s = (const float*)(smem + OFF_B1S) + hf * 16;
                #pragma unroll
                for (int k = 0; k < 16; k++) hval[k] = b1s[k];
                const float4* er = (const float4*)(edge_attr + (size_t)eidc * 16);
                #pragma unroll
                for (int qq = 0; qq < 4; qq++) {
                    float4 q = er[qq];
                    float ev[4] = {q.x, q.y, q.z, q.w};
                    #pragma unroll
                    for (int dj = 0; dj < 4; dj++) {
                        int d = qq * 4 + dj;
                        #pragma unroll
                        for (int k = 0; k < 16; k++)
                            hval[k] = fmaf(ev[dj], W1s[d * 32 + k], hval[k]);
                    }
                }
                #pragma unroll
                for (int k = 0; k < 16; k++) hval[k] = fmaxf(hval[k], SLOPE * hval[k]);
            }

            // A row: fp16(h); half hf writes k = hf*16 .. hf*16+15  (32 bytes)
            union { __half2 h2[8]; uint4 u4[2]; } pk;
            #pragma unroll
            for (int j = 0; j < 8; j++)
                pk.h2[j] = __halves2half2(__float2half_rn(hval[2 * j]),
                                          __float2half_rn(hval[2 * j + 1]));
            char* arow = smem + OFF_AS + e * ASTRIDE + hf * 32;
            *(uint4*)(arow)      = pk.u4[0];
            *(uint4*)(arow + 16) = pk.u4[1];
        }
        __syncthreads();

        // ============ phase 2: fp16 MMA + fused epilogue ============
        uint32_t af[2][2][4];   // [row-chunk][k-half]
        #pragma unroll
        for (int c = 0; c < 2; c++) {
            ldsm4(af[c][0], a_base + c * (16 * ASTRIDE));
            ldsm4(af[c][1], a_base + c * (16 * ASTRIDE) + 32);
        }
        const int r0 = Mw * 32 + (lane >> 2);

        float msg[2][2][4][2];
        #pragma unroll
        for (int a1 = 0; a1 < 2; a1++)
            #pragma unroll
            for (int a2 = 0; a2 < 2; a2++)
                #pragma unroll
                for (int a3 = 0; a3 < 4; a3++)
                    { msg[a1][a2][a3][0] = 0.f; msg[a1][a2][a3][1] = 0.f; }

        for (int nbo = 0; nbo < 64; nbo += 4) {
            #pragma unroll
            for (int nbq = 0; nbq < 4; nbq++) {
                int nb = nbo + nbq;
                int n0 = Nw * 512 + nb * 8;
                uint32_t ba = b_base + (uint32_t)(nb * 8) * BSTRIDE;
                uint32_t g0[2], g1[2];
                ldsm2(g0, ba);         // W k0-15
                ldsm2(g1, ba + 32);    // W k16-31
                float2 b2v = *(const float2*)(b2s + n0 + (lane & 3) * 2);
                int ii = n0 >> 5;

                float c0[4] = {0.f,0.f,0.f,0.f};
                float c1[4] = {0.f,0.f,0.f,0.f};
                mma_f16(c0, af[0][0], g0);  mma_f16(c1, af[1][0], g0);
                mma_f16(c0, af[0][1], g1);  mma_f16(c1, af[1][1], g1);

                float xv00 = xj[ii * 128 + r0];
                float xv01 = xj[ii * 128 + r0 + 8];
                float xv10 = xj[ii * 128 + r0 + 16];
                float xv11 = xj[ii * 128 + r0 + 24];
                float v;
                v = c0[0] + b2v.x; v = fmaxf(v, SLOPE * v);
                msg[0][0][nbq][0] = fmaf(xv00, v, msg[0][0][nbq][0]);
                v = c0[1] + b2v.y; v = fmaxf(v, SLOPE * v);
                msg[0][0][nbq][1] = fmaf(xv00, v, msg[0][0][nbq][1]);
                v = c0[2] + b2v.x; v = fmaxf(v, SLOPE * v);
                msg[0][1][nbq][0] = fmaf(xv01, v, msg[0][1][nbq][0]);
                v = c0[3] + b2v.y; v = fmaxf(v, SLOPE * v);
                msg[0][1][nbq][1] = fmaf(xv01, v, msg[0][1][nbq][1]);
                v = c1[0] + b2v.x; v = fmaxf(v, SLOPE * v);
                msg[1][0][nbq][0] = fmaf(xv10, v, msg[1][0][nbq][0]);
                v = c1[1] + b2v.y; v = fmaxf(v, SLOPE * v);
                msg[1][0][nbq][1] = fmaf(xv10, v, msg[1][0][nbq][1]);
                v = c1[2] + b2v.x; v = fmaxf(v, SLOPE * v);
                msg[1][1][nbq][0] = fmaf(xv11, v, msg[1][1][nbq][0]);
                v = c1[3] + b2v.y; v = fmaxf(v, SLOPE * v);
                msg[1][1][nbq][1] = fmaf(xv11, v, msg[1][1][nbq][1]);
            }
        }

        // ============ phase 3: msg -> smem, sum halves, coalesced atomics ============
        #pragma unroll
        for (int ch = 0; ch < 2; ch++)
            #pragma unroll
            for (int rh = 0; rh < 2; rh++)
                #pragma unroll
                for (int j = 0; j < 4; j++)
                    #pragma unroll
                    for (int d = 0; d < 2; d++) {
                        int row = Mw * 32 + ch * 16 + rh * 8 + (lane >> 2);
                        int o = (lane & 3) * 2 + 8 * j + d;
                        ms[row * 33 + o] = msg[ch][rh][j][d];
                    }
        __syncthreads();

        #pragma unroll 1
        for (int ee = 0; ee < 16; ee++) {
            int e2 = wid * 16 + ee;
            int dd = dst_s[e2];
            if (dd >= 0)
                atomicAdd(out + (size_t)dd * 32 + lane,
                          ms0[e2 * 33 + lane] + ms1[e2 * 33 + lane]);
        }
        __syncthreads();   // protect dst_s/xj/A before next tile's writes
    }
}

// ---------------------------------------------------------------------------
extern "C" void kernel_launch(void* const* d_in, const int* in_sizes, int n_in,
                              void* d_out, int out_size)
{
    const float* x    = (const float*)d_in[0];
    const int*   ei   = (const int*)d_in[1];
    const float* ea   = (const float*)d_in[2];
    const float* W1   = (const float*)d_in[4];
    const float* b1   = (const float*)d_in[5];
    const float* g1   = (const float*)d_in[6];
    const float* be1  = (const float*)d_in[7];
    const float* m1   = (const float*)d_in[8];
    const float* v1   = (const float*)d_in[9];
    const float* W2   = (const float*)d_in[10];
    const float* b2   = (const float*)d_in[11];
    const float* g2   = (const float*)d_in[12];
    const float* be2  = (const float*)d_in[13];
    const float* m2   = (const float*)d_in[14];
    const float* v2   = (const float*)d_in[15];
    const float* root = (const float*)d_in[16];
    const float* bias = (const float*)d_in[17];
    float* out = (float*)d_out;

    cudaFuncSetAttribute(edge_kernel, cudaFuncAttributeMaxDynamicSharedMemorySize, SMEM_BYTES);

    fold_kernel<<<128, 256>>>(W1, b1, g1, be1, m1, v1, W2, b2, g2, be2, m2, v2, ei);
    init_kernel<<<(NN + 7) / 8, 256>>>(x, root, bias, out);
    edge_kernel<<<EGRID, 256, SMEM_BYTES>>>(x, ei, ea, out);
}

// round 9
// speedup vs baseline: 3.4665x; 1.0150x over previous
#include <cuda_runtime.h>
#include <cuda_fp16.h>
#include <cstdint>

#define NN 50000
#define NE 200000
#define EPSV 1e-5f
#define SLOPE 0.01f
#define NTILES 1563          // ceil(NE/128)
#define EGRID 148

#define BSTRIDE 80           // B tile row stride (64B data + 16 pad)
#define ASTRIDE 80           // A tile row stride (64B data + 16 pad)

// ---- dynamic smem byte offsets ----
#define OFF_BS   0           // B [1024 n][32 fp16]                 81920
#define OFF_AS   81920       // A [128 e][32 fp16]                  10240
#define OFF_XJ   92160       // xjT [32 i][128 e] float             16384
#define OFF_MSG  108544      // msg [4 Nw][128 e][33] float         67584
#define OFF_B2S  176128      // 1024 float
#define OFF_W1S  180224      // 512 float
#define OFF_B1S  182272      // 32 float
#define OFF_DST  182400      // 128 int
#define SMEM_BYTES 182912

// preprocessed weights
__device__ __half g_Bh[1024 * 32];   // [n][k] fp16(W2f[k][n] * bn-scale)
__device__ float g_b2f[1024];
__device__ float g_W1f[512];         // [d][k]
__device__ float g_b1f[32];
__device__ int   g_is64;

// ---------------- helpers ----------------
static __device__ __forceinline__ uint32_t smem_u32(const void* p) {
    uint32_t a;
    asm("{ .reg .u64 t; cvta.to.shared.u64 t, %1; cvt.u32.u64 %0, t; }" : "=r"(a) : "l"(p));
    return a;
}
static __device__ __forceinline__ void ldsm4(uint32_t r[4], uint32_t addr) {
    asm volatile("ldmatrix.sync.aligned.m8n8.x4.shared.b16 {%0,%1,%2,%3}, [%4];"
        : "=r"(r[0]), "=r"(r[1]), "=r"(r[2]), "=r"(r[3]) : "r"(addr));
}
static __device__ __forceinline__ void ldsm2(uint32_t r[2], uint32_t addr) {
    asm volatile("ldmatrix.sync.aligned.m8n8.x2.shared.b16 {%0,%1}, [%2];"
        : "=r"(r[0]), "=r"(r[1]) : "r"(addr));
}
static __device__ __forceinline__ void mma_f16(float c[4], const uint32_t a[4], const uint32_t b[2]) {
    asm volatile("mma.sync.aligned.m16n8k16.row.col.f32.f16.f16.f32 "
        "{%0,%1,%2,%3}, {%4,%5,%6,%7}, {%8,%9}, {%0,%1,%2,%3};"
        : "+f"(c[0]), "+f"(c[1]), "+f"(c[2]), "+f"(c[3])
        : "r"(a[0]), "r"(a[1]), "r"(a[2]), "r"(a[3]), "r"(b[0]), "r"(b[1]));
}

// prefetch next tile's scattered loads (indices + x row) into registers
static __device__ __forceinline__ void prefetch_tile(
    int t, int e, int qf, int is64,
    const int* __restrict__ ei32, const float* __restrict__ x,
    int& pdst, float4& px0, float4& px1)
{
    int eid = t * 128 + e;
    int valid = eid < NE;
    int eidc = valid ? eid : NE - 1;
    int src, dd;
    if (is64) { src = ei32[2 * eidc]; dd = ei32[2 * (NE + eidc)]; }
    else      { src = ei32[eidc];     dd = ei32[NE + eidc]; }
    pdst = valid ? dd : -1;
    const float4* xr = (const float4*)(x + (size_t)src * 32);
    px0 = xr[qf * 2];
    px1 = xr[qf * 2 + 1];
}

// ---------------------------------------------------------------------------
// fold: BN into weights; W2f -> single fp16.
// ---------------------------------------------------------------------------
__global__ void fold_kernel(const float* __restrict__ W1, const float* __restrict__ b1,
                            const float* __restrict__ g1, const float* __restrict__ be1,
                            const float* __restrict__ m1, const float* __restrict__ v1,
                            const float* __restrict__ W2, const float* __restrict__ b2,
                            const float* __restrict__ g2, const float* __restrict__ be2,
                            const float* __restrict__ m2, const float* __restrict__ v2,
                            const int* __restrict__ ei32)
{
    int idx = blockIdx.x * blockDim.x + threadIdx.x;   // 0..32767
    if (idx >= 32768) return;
    int n = idx & 1023;
    int k = idx >> 10;                                 // 0..31
    float s = g2[n] * rsqrtf(v2[n] + EPSV);
    g_Bh[n * 32 + k] = __float2half_rn(W2[k * 1024 + n] * s);
    if (k == 0) {
        g_b2f[n] = (b2[n] - m2[n]) * s + be2[n];
        if (n < 32) {
            float s1 = g1[n] * rsqrtf(v1[n] + EPSV);
            g_b1f[n] = (b1[n] - m1[n]) * s1 + be1[n];
            #pragma unroll
            for (int d = 0; d < 16; d++)
                g_W1f[d * 32 + n] = W1[d * 32 + n] * s1;
        }
        if (n == 0) {
            int all0 = 1;
            for (int i = 0; i < 64; i++)
                if (ei32[2 * i + 1] != 0) { all0 = 0; break; }
            g_is64 = all0;
        }
    }
}

// ---------------------------------------------------------------------------
// out[n,:] = bias + x[n,:] @ root
// ---------------------------------------------------------------------------
__global__ void init_kernel(const float* __restrict__ x,
                            const float* __restrict__ root,
                            const float* __restrict__ bias,
                            float* __restrict__ out)
{
    __shared__ float root_s[1024];
    __shared__ float bias_s[32];
    int t = threadIdx.x;
    for (int i = t; i < 1024; i += blockDim.x) root_s[i] = root[i];
    if (t < 32) bias_s[t] = bias[t];
    __syncthreads();
    int lane = t & 31, w = t >> 5;
    int n = blockIdx.x * (blockDim.x >> 5) + w;
    if (n >= NN) return;
    float xv = x[n * 32 + lane];
    float acc = bias_s[lane];
    #pragma unroll
    for (int i = 0; i < 32; i++)
        acc = fmaf(__shfl_sync(0xffffffffu, xv, i), root_s[i * 32 + lane], acc);
    out[n * 32 + lane] = acc;
}

// ---------------------------------------------------------------------------
// Persistent fused edge kernel: 512 thr, fp16 mma.sync + prefetch pipeline.
// ---------------------------------------------------------------------------
extern __shared__ char smem[];

__global__ void __launch_bounds__(512, 1)
edge_kernel(const float* __restrict__ x,
            const int*   __restrict__ ei32,
            const float* __restrict__ edge_attr,
            float* __restrict__ out)
{
    const int tid = threadIdx.x;
    const int lane = tid & 31, wid = tid >> 5;
    const int Mw = wid & 3, Nw = wid >> 2;              // 4 M-warps x 4 N-warps
    uint32_t su = smem_u32(smem);

    // ---- persistent copies: B, b2f, W1f, b1f ----
    {
        const int4* bs = (const int4*)g_Bh;
        for (int i = tid; i < 4096; i += 512) {        // 1024 rows x 4 int4
            int n = i >> 2, seg = i & 3;
            *(int4*)(smem + OFF_BS + n * BSTRIDE + seg * 16) = bs[i];
        }
        float* b2w = (float*)(smem + OFF_B2S);
        for (int i = tid; i < 1024; i += 512) b2w[i] = g_b2f[i];
        float* w1w = (float*)(smem + OFF_W1S);
        if (tid < 512) w1w[tid] = g_W1f[tid];
        if (tid < 32) ((float*)(smem + OFF_B1S))[tid] = g_b1f[tid];
    }
    const int is64 = g_is64;
    __syncthreads();

    // ldmatrix base addresses
    uint32_t a_base = su + OFF_AS + (uint32_t)(Mw * 32 + (lane & 15)) * ASTRIDE + (lane >> 4) * 16;
    uint32_t b_base = su + OFF_BS + (uint32_t)(Nw * 256 + (lane & 7)) * BSTRIDE + ((lane >> 3) & 1) * 16;

    const float* b2s = (const float*)(smem + OFF_B2S);
    const float* xj  = (const float*)(smem + OFF_XJ);
    float* ms        = (float*)(smem + OFF_MSG) + Nw * (128 * 33);
    const float* msb = (const float*)(smem + OFF_MSG);
    int* dst_s       = (int*)(smem + OFF_DST);

    const int e  = tid >> 2;      // edge within tile (4 threads per edge)
    const int qf = tid & 3;       // quarter: k-range [qf*8, qf*8+8)

    int pf_dst; float4 px0, px1;
    int tile = blockIdx.x;
    if (tile < NTILES)
        prefetch_tile(tile, e, qf, is64, ei32, x, pf_dst, px0, px1);

    for (; tile < NTILES; tile += gridDim.x) {
        // ============ phase 1 (compute-only; scattered data prefetched) ============
        {
            if (qf == 0) dst_s[e] = pf_dst;

            // xjT stores from prefetched x row
            float* xjw = (float*)(smem + OFF_XJ);
            int i0 = qf * 8;
            xjw[(i0 + 0) * 128 + e] = px0.x;
            xjw[(i0 + 1) * 128 + e] = px0.y;
            xjw[(i0 + 2) * 128 + e] = px0.z;
            xjw[(i0 + 3) * 128 + e] = px0.w;
            xjw[(i0 + 4) * 128 + e] = px1.x;
            xjw[(i0 + 5) * 128 + e] = px1.y;
            xjw[(i0 + 6) * 128 + e] = px1.z;
            xjw[(i0 + 7) * 128 + e] = px1.w;

            // edge_attr load (sequential, L2-friendly)
            int eidc = tile * 128 + e;
            if (eidc >= NE) eidc = NE - 1;
            const float4* er = (const float4*)(edge_attr + (size_t)eidc * 16);
            float4 q0 = er[0], q1 = er[1], q2 = er[2], q3 = er[3];
            float eav[16] = {q0.x,q0.y,q0.z,q0.w, q1.x,q1.y,q1.z,q1.w,
                             q2.x,q2.y,q2.z,q2.w, q3.x,q3.y,q3.z,q3.w};

            // layer 1: this thread's 8 k-values
            float hval[8];
            const float* W1s = (const float*)(smem + OFF_W1S) + qf * 8;
            const float* b1s = (const float*)(smem + OFF_B1S) + qf * 8;
            #pragma unroll
            for (int k = 0; k < 8; k++) hval[k] = b1s[k];
            #pragma unroll
            for (int d = 0; d < 16; d++) {
                float a = eav[d];
                #pragma unroll
                for (int k = 0; k < 8; k++)
                    hval[k] = fmaf(a, W1s[d * 32 + k], hval[k]);
            }
            #pragma unroll
            for (int k = 0; k < 8; k++) hval[k] = fmaxf(hval[k], SLOPE * hval[k]);

            // A row segment: 8 fp16 = 16 bytes at offset qf*16
            union { __half2 h2[4]; uint4 u4; } pk;
            #pragma unroll
            for (int j = 0; j < 4; j++)
                pk.h2[j] = __halves2half2(__float2half_rn(hval[2 * j]),
                                          __float2half_rn(hval[2 * j + 1]));
            *(uint4*)(smem + OFF_AS + e * ASTRIDE + qf * 16) = pk.u4;
        }
        __syncthreads();

        // ============ phase 2: A-frags, prefetch next tile, MMA + epilogue ============
        uint32_t af[2][2][4];   // [row-chunk][k-half]
        #pragma unroll
        for (int c = 0; c < 2; c++) {
            ldsm4(af[c][0], a_base + c * (16 * ASTRIDE));
            ldsm4(af[c][1], a_base + c * (16 * ASTRIDE) + 32);
        }

        int nt = tile + gridDim.x;
        if (nt < NTILES)
            prefetch_tile(nt, e, qf, is64, ei32, x, pf_dst, px0, px1);

        const int r0 = Mw * 32 + (lane >> 2);

        float msg[2][2][4][2];
        #pragma unroll
        for (int a1 = 0; a1 < 2; a1++)
            #pragma unroll
            for (int a2 = 0; a2 < 2; a2++)
                #pragma unroll
                for (int a3 = 0; a3 < 4; a3++)
                    { msg[a1][a2][a3][0] = 0.f; msg[a1][a2][a3][1] = 0.f; }

        #pragma unroll 4
        for (int nb = 0; nb < 32; nb++) {
            int n0 = Nw * 256 + nb * 8;
            uint32_t ba = b_base + (uint32_t)(nb * 8) * BSTRIDE;
            uint32_t g0[2], g1[2];
            ldsm2(g0, ba);         // W k0-15
            ldsm2(g1, ba + 32);    // W k16-31
            float2 b2v = *(const float2*)(b2s + n0 + (lane & 3) * 2);
            int ii = n0 >> 5;
            int nbq = nb & 3;

            float c0[4] = {0.f,0.f,0.f,0.f};
            float c1[4] = {0.f,0.f,0.f,0.f};
            mma_f16(c0, af[0][0], g0);  mma_f16(c1, af[1][0], g0);
            mma_f16(c0, af[0][1], g1);  mma_f16(c1, af[1][1], g1);

            float xv00 = xj[ii * 128 + r0];
            float xv01 = xj[ii * 128 + r0 + 8];
            float xv10 = xj[ii * 128 + r0 + 16];
            float xv11 = xj[ii * 128 + r0 + 24];
            float v;
            v = c0[0] + b2v.x; v = fmaxf(v, SLOPE * v);
            msg[0][0][nbq][0] = fmaf(xv00, v, msg[0][0][nbq][0]);
            v = c0[1] + b2v.y; v = fmaxf(v, SLOPE * v);
            msg[0][0][nbq][1] = fmaf(xv00, v, msg[0][0][nbq][1]);
            v = c0[2] + b2v.x; v = fmaxf(v, SLOPE * v);
            msg[0][1][nbq][0] = fmaf(xv01, v, msg[0][1][nbq][0]);
            v = c0[3] + b2v.y; v = fmaxf(v, SLOPE * v);
            msg[0][1][nbq][1] = fmaf(xv01, v, msg[0][1][nbq][1]);
            v = c1[0] + b2v.x; v = fmaxf(v, SLOPE * v);
            msg[1][0][nbq][0] = fmaf(xv10, v, msg[1][0][nbq][0]);
            v = c1[1] + b2v.y; v = fmaxf(v, SLOPE * v);
            msg[1][0][nbq][1] = fmaf(xv10, v, msg[1][0][nbq][1]);
            v = c1[2] + b2v.x; v = fmaxf(v, SLOPE * v);
            msg[1][1][nbq][0] = fmaf(xv11, v, msg[1][1][nbq][0]);
            v = c1[3] + b2v.y; v = fmaxf(v, SLOPE * v);
            msg[1][1][nbq][1] = fmaf(xv11, v, msg[1][1][nbq][1]);
        }

        // ============ phase 3: msg -> smem (per-Nw copy), sum 4, atomics ============
        #pragma unroll
        for (int ch = 0; ch < 2; ch++)
            #pragma unroll
            for (int rh = 0; rh < 2; rh++)
                #pragma unroll
                for (int j = 0; j < 4; j++)
                    #pragma unroll
                    for (int d = 0; d < 2; d++) {
                        int row = Mw * 32 + ch * 16 + rh * 8 + (lane >> 2);
                        int o = (lane & 3) * 2 + 8 * j + d;
                        ms[row * 33 + o] = msg[ch][rh][j][d];
                    }
        __syncthreads();

        #pragma unroll 1
        for (int ee = 0; ee < 8; ee++) {
            int e2 = wid * 8 + ee;
            int dd = dst_s[e2];
            if (dd >= 0) {
                float v = msb[e2 * 33 + lane]
                        + msb[128 * 33 + e2 * 33 + lane]
                        + msb[2 * 128 * 33 + e2 * 33 + lane]
                        + msb[3 * 128 * 33 + e2 * 33 + lane];
                atomicAdd(out + (size_t)dd * 32 + lane, v);
            }
        }
        __syncthreads();   // protect dst_s/xj/A before next tile's writes
    }
}

// ---------------------------------------------------------------------------
extern "C" void kernel_launch(void* const* d_in, const int* in_sizes, int n_in,
                              void* d_out, int out_size)
{
    const float* x    = (const float*)d_in[0];
    const int*   ei   = (const int*)d_in[1];
    const float* ea   = (const float*)d_in[2];
    const float* W1   = (const float*)d_in[4];
    const float* b1   = (const float*)d_in[5];
    const float* g1   = (const float*)d_in[6];
    const float* be1  = (const float*)d_in[7];
    const float* m1   = (const float*)d_in[8];
    const float* v1   = (const float*)d_in[9];
    const float* W2   = (const float*)d_in[10];
    const float* b2   = (const float*)d_in[11];
    const float* g2   = (const float*)d_in[12];
    const float* be2  = (const float*)d_in[13];
    const float* m2   = (const float*)d_in[14];
    const float* v2   = (const float*)d_in[15];
    const float* root = (const float*)d_in[16];
    const float* bias = (const float*)d_in[17];
    float* out = (float*)d_out;

    cudaFuncSetAttribute(edge_kernel, cudaFuncAttributeMaxDynamicSharedMemorySize, SMEM_BYTES);

    fold_kernel<<<128, 256>>>(W1, b1, g1, be1, m1, v1, W2, b2, g2, be2, m2, v2, ei);
    init_kernel<<<(NN + 7) / 8, 256>>>(x, root, bias, out);
    edge_kernel<<<EGRID, 512, SMEM_BYTES>>>(x, ei, ea, out);
}

// round 11
// speedup vs baseline: 3.4771x; 1.0031x over previous
#include <cuda_runtime.h>
#include <cuda_fp16.h>
#include <cstdint>

#define NN 50000
#define NE 200000
#define EPSV 1e-5f
#define SLOPE 0.01f
#define NTILES 1563          // ceil(NE/128)
#define EGRID 148

#define BSTRIDE 80           // B tile row stride (64B data + 16 pad)
#define ASTRIDE 80           // A tile row stride (64B data + 16 pad)

// ---- dynamic smem byte offsets ----
#define OFF_BS   0           // B [1024 n][32 fp16]                 81920
#define OFF_AS   81920       // A [128 e][32 fp16]                  10240
#define OFF_XJ   92160       // xjT [32 i][128 e] float             16384
#define OFF_MSG  108544      // msg [4 Nw][128 e][33] float         67584
#define OFF_B2S  176128      // 1024 float
#define OFF_W1S  180224      // 512 float
#define OFF_B1S  182272      // 32 float
#define OFF_DST  182400      // 128 int
#define SMEM_BYTES 182912

// preprocessed weights
__device__ __half g_Bh[1024 * 32];   // [n][k] fp16(W2f[k][n] * bn-scale)
__device__ float g_b2f[1024];
__device__ float g_W1f[512];         // [d][k]
__device__ float g_b1f[32];
__device__ int   g_is64;

// ---------------- helpers ----------------
static __device__ __forceinline__ uint32_t smem_u32(const void* p) {
    uint32_t a;
    asm("{ .reg .u64 t; cvta.to.shared.u64 t, %1; cvt.u32.u64 %0, t; }" : "=r"(a) : "l"(p));
    return a;
}
static __device__ __forceinline__ void ldsm4(uint32_t r[4], uint32_t addr) {
    asm volatile("ldmatrix.sync.aligned.m8n8.x4.shared.b16 {%0,%1,%2,%3}, [%4];"
        : "=r"(r[0]), "=r"(r[1]), "=r"(r[2]), "=r"(r[3]) : "r"(addr));
}
static __device__ __forceinline__ void mma_f16(float c[4], const uint32_t a[4], const uint32_t* b) {
    asm volatile("mma.sync.aligned.m16n8k16.row.col.f32.f16.f16.f32 "
        "{%0,%1,%2,%3}, {%4,%5,%6,%7}, {%8,%9}, {%0,%1,%2,%3};"
        : "+f"(c[0]), "+f"(c[1]), "+f"(c[2]), "+f"(c[3])
        : "r"(a[0]), "r"(a[1]), "r"(a[2]), "r"(a[3]), "r"(b[0]), "r"(b[1]));
}

// prefetch next tile's scattered loads (indices + x row) into registers
static __device__ __forceinline__ void prefetch_tile(
    int t, int e, int qf, int is64,
    const int* __restrict__ ei32, const float* __restrict__ x,
    int& pdst, float4& px0, float4& px1)
{
    int eid = t * 128 + e;
    int valid = eid < NE;
    int eidc = valid ? eid : NE - 1;
    int src, dd;
    if (is64) { src = ei32[2 * eidc]; dd = ei32[2 * (NE + eidc)]; }
    else      { src = ei32[eidc];     dd = ei32[NE + eidc]; }
    pdst = valid ? dd : -1;
    const float4* xr = (const float4*)(x + (size_t)src * 32);
    px0 = xr[qf * 2];
    px1 = xr[qf * 2 + 1];
}

// ---------------------------------------------------------------------------
// fold: BN into weights; W2f -> single fp16.
// ---------------------------------------------------------------------------
__global__ void fold_kernel(const float* __restrict__ W1, const float* __restrict__ b1,
                            const float* __restrict__ g1, const float* __restrict__ be1,
                            const float* __restrict__ m1, const float* __restrict__ v1,
                            const float* __restrict__ W2, const float* __restrict__ b2,
                            const float* __restrict__ g2, const float* __restrict__ be2,
                            const float* __restrict__ m2, const float* __restrict__ v2,
                            const int* __restrict__ ei32)
{
    int idx = blockIdx.x * blockDim.x + threadIdx.x;   // 0..32767
    if (idx >= 32768) return;
    int n = idx & 1023;
    int k = idx >> 10;                                 // 0..31
    float s = g2[n] * rsqrtf(v2[n] + EPSV);
    g_Bh[n * 32 + k] = __float2half_rn(W2[k * 1024 + n] * s);
    if (k == 0) {
        g_b2f[n] = (b2[n] - m2[n]) * s + be2[n];
        if (n < 32) {
            float s1 = g1[n] * rsqrtf(v1[n] + EPSV);
            g_b1f[n] = (b1[n] - m1[n]) * s1 + be1[n];
            #pragma unroll
            for (int d = 0; d < 16; d++)
                g_W1f[d * 32 + n] = W1[d * 32 + n] * s1;
        }
        if (n == 0) {
            int all0 = 1;
            for (int i = 0; i < 64; i++)
                if (ei32[2 * i + 1] != 0) { all0 = 0; break; }
            g_is64 = all0;
        }
    }
}

// ---------------------------------------------------------------------------
// out[n,:] = bias + x[n,:] @ root
// ---------------------------------------------------------------------------
__global__ void init_kernel(const float* __restrict__ x,
                            const float* __restrict__ root,
                            const float* __restrict__ bias,
                            float* __restrict__ out)
{
    __shared__ float root_s[1024];
    __shared__ float bias_s[32];
    int t = threadIdx.x;
    for (int i = t; i < 1024; i += blockDim.x) root_s[i] = root[i];
    if (t < 32) bias_s[t] = bias[t];
    __syncthreads();
    int lane = t & 31, w = t >> 5;
    int n = blockIdx.x * (blockDim.x >> 5) + w;
    if (n >= NN) return;
    float xv = x[n * 32 + lane];
    float acc = bias_s[lane];
    #pragma unroll
    for (int i = 0; i < 32; i++)
        acc = fmaf(__shfl_sync(0xffffffffu, xv, i), root_s[i * 32 + lane], acc);
    out[n * 32 + lane] = acc;
}

// ---------------------------------------------------------------------------
// Persistent fused edge kernel: 512 thr, lean-epilogue fp16 mma.sync.
// ---------------------------------------------------------------------------
extern __shared__ char smem[];

__global__ void __launch_bounds__(512, 1)
edge_kernel(const float* __restrict__ x,
            const int*   __restrict__ ei32,
            const float* __restrict__ edge_attr,
            float* __restrict__ out)
{
    const int tid = threadIdx.x;
    const int lane = tid & 31, wid = tid >> 5;
    const int Mw = wid & 3, Nw = wid >> 2;              // 4 M-warps x 4 N-warps
    uint32_t su = smem_u32(smem);

    // ---- persistent copies: B, b2f, W1f, b1f ----
    {
        const int4* bs = (const int4*)g_Bh;
        for (int i = tid; i < 4096; i += 512) {        // 1024 rows x 4 int4
            int n = i >> 2, seg = i & 3;
            *(int4*)(smem + OFF_BS + n * BSTRIDE + seg * 16) = bs[i];
        }
        float* b2w = (float*)(smem + OFF_B2S);
        for (int i = tid; i < 1024; i += 512) b2w[i] = g_b2f[i];
        float* w1w = (float*)(smem + OFF_W1S);
        if (tid < 512) w1w[tid] = g_W1f[tid];
        if (tid < 32) ((float*)(smem + OFF_B1S))[tid] = g_b1f[tid];
    }
    const int is64 = g_is64;
    __syncthreads();

    // ldmatrix base addresses
    uint32_t a_base = su + OFF_AS + (uint32_t)(Mw * 32 + (lane & 15)) * ASTRIDE + (lane >> 4) * 16;
    // B ldsm4: lane&7 = row, lane>>3 = 16B chunk (k0-7|k8-15|k16-23|k24-31)
    uint32_t b_base = su + OFF_BS + (uint32_t)(Nw * 256 + (lane & 7)) * BSTRIDE + (lane >> 3) * 16;

    const float* b2s = (const float*)(smem + OFF_B2S);
    const float* xj  = (const float*)(smem + OFF_XJ);
    float* ms        = (float*)(smem + OFF_MSG) + Nw * (128 * 33);
    const float* msb = (const float*)(smem + OFF_MSG);
    int* dst_s       = (int*)(smem + OFF_DST);

    const int e  = tid >> 2;      // edge within tile (4 threads per edge)
    const int qf = tid & 3;       // quarter: k-range [qf*8, qf*8+8)

    int pf_dst; float4 px0, px1;
    int tile = blockIdx.x;
    if (tile < NTILES)
        prefetch_tile(tile, e, qf, is64, ei32, x, pf_dst, px0, px1);

    for (; tile < NTILES; tile += gridDim.x) {
        // ============ phase 1 (compute-only; scattered data prefetched) ============
        {
            if (qf == 0) dst_s[e] = pf_dst;

            // xjT stores from prefetched x row
            float* xjw = (float*)(smem + OFF_XJ);
            int i0 = qf * 8;
            xjw[(i0 + 0) * 128 + e] = px0.x;
            xjw[(i0 + 1) * 128 + e] = px0.y;
            xjw[(i0 + 2) * 128 + e] = px0.z;
            xjw[(i0 + 3) * 128 + e] = px0.w;
            xjw[(i0 + 4) * 128 + e] = px1.x;
            xjw[(i0 + 5) * 128 + e] = px1.y;
            xjw[(i0 + 6) * 128 + e] = px1.z;
            xjw[(i0 + 7) * 128 + e] = px1.w;

            // edge_attr load (sequential, L2-friendly)
            int eidc = tile * 128 + e;
            if (eidc >= NE) eidc = NE - 1;
            const float4* er = (const float4*)(edge_attr + (size_t)eidc * 16);
            float4 q0 = er[0], q1 = er[1], q2 = er[2], q3 = er[3];
            float eav[16] = {q0.x,q0.y,q0.z,q0.w, q1.x,q1.y,q1.z,q1.w,
                             q2.x,q2.y,q2.z,q2.w, q3.x,q3.y,q3.z,q3.w};

            // layer 1: this thread's 8 k-values
            float hval[8];
            const float* W1s = (const float*)(smem + OFF_W1S) + qf * 8;
            const float* b1s = (const float*)(smem + OFF_B1S) + qf * 8;
            #pragma unroll
            for (int k = 0; k < 8; k++) hval[k] = b1s[k];
            #pragma unroll
            for (int d = 0; d < 16; d++) {
                float a = eav[d];
                #pragma unroll
                for (int k = 0; k < 8; k++)
                    hval[k] = fmaf(a, W1s[d * 32 + k], hval[k]);
            }
            #pragma unroll
            for (int k = 0; k < 8; k++) hval[k] = fmaxf(hval[k], SLOPE * hval[k]);

            // A row segment: 8 fp16 = 16 bytes at offset qf*16
            union { __half2 h2[4]; uint4 u4; } pk;
            #pragma unroll
            for (int j = 0; j < 4; j++)
                pk.h2[j] = __halves2half2(__float2half_rn(hval[2 * j]),
                                          __float2half_rn(hval[2 * j + 1]));
            *(uint4*)(smem + OFF_AS + e * ASTRIDE + qf * 16) = pk.u4;
        }
        __syncthreads();

        // ============ phase 2: A-frags, dst->regs, prefetch, MMA + epilogue ============
        uint32_t af[2][2][4];   // [row-chunk][k-half]
        #pragma unroll
        for (int c = 0; c < 2; c++) {
            ldsm4(af[c][0], a_base + c * (16 * ASTRIDE));
            ldsm4(af[c][1], a_base + c * (16 * ASTRIDE) + 32);
        }

        // own warp's dst entries -> registers (frees the tail barrier)
        int dreg[8];
        #pragma unroll
        for (int ee = 0; ee < 8; ee++) dreg[ee] = dst_s[wid * 8 + ee];

        int nt = tile + gridDim.x;
        if (nt < NTILES)
            prefetch_tile(nt, e, qf, is64, ei32, x, pf_dst, px0, px1);

        const int r0 = Mw * 32 + (lane >> 2);

        float msg[2][2][4][2];
        #pragma unroll
        for (int a1 = 0; a1 < 2; a1++)
            #pragma unroll
            for (int a2 = 0; a2 < 2; a2++)
                #pragma unroll
                for (int a3 = 0; a3 < 4; a3++)
                    { msg[a1][a2][a3][0] = 0.f; msg[a1][a2][a3][1] = 0.f; }

        #pragma unroll 2
        for (int nbo = 0; nbo < 8; nbo++) {
            // ii fixed for the 4 nb in this group: hoist xv loads
            int ii = Nw * 8 + nbo;
            float xv00 = xj[ii * 128 + r0];
            float xv01 = xj[ii * 128 + r0 + 8];
            float xv10 = xj[ii * 128 + r0 + 16];
            float xv11 = xj[ii * 128 + r0 + 24];

            #pragma unroll
            for (int nbq = 0; nbq < 4; nbq++) {
                int nb = nbo * 4 + nbq;
                int n0 = Nw * 256 + nb * 8;
                uint32_t gg[4];                         // g0 = gg[0..1], g1 = gg[2..3]
                ldsm4(gg, b_base + (uint32_t)(nb * 8) * BSTRIDE);
                float2 b2v = *(const float2*)(b2s + n0 + (lane & 3) * 2);

                // bias folded into accumulator init
                float c0[4] = {b2v.x, b2v.y, b2v.x, b2v.y};
                float c1[4] = {b2v.x, b2v.y, b2v.x, b2v.y};
                mma_f16(c0, af[0][0], gg);      mma_f16(c1, af[1][0], gg);
                mma_f16(c0, af[0][1], gg + 2);  mma_f16(c1, af[1][1], gg + 2);

                float v;
                v = fmaxf(c0[0], SLOPE * c0[0]);
                msg[0][0][nbq][0] = fmaf(xv00, v, msg[0][0][nbq][0]);
                v = fmaxf(c0[1], SLOPE * c0[1]);
                msg[0][0][nbq][1] = fmaf(xv00, v, msg[0][0][nbq][1]);
                v = fmaxf(c0[2], SLOPE * c0[2]);
                msg[0][1][nbq][0] = fmaf(xv01, v, msg[0][1][nbq][0]);
                v = fmaxf(c0[3], SLOPE * c0[3]);
                msg[0][1][nbq][1] = fmaf(xv01, v, msg[0][1][nbq][1]);
                v = fmaxf(c1[0], SLOPE * c1[0]);
                msg[1][0][nbq][0] = fmaf(xv10, v, msg[1][0][nbq][0]);
                v = fmaxf(c1[1], SLOPE * c1[1]);
                msg[1][0][nbq][1] = fmaf(xv10, v, msg[1][0][nbq][1]);
                v = fmaxf(c1[2], SLOPE * c1[2]);
                msg[1][1][nbq][0] = fmaf(xv11, v, msg[1][1][nbq][0]);
                v = fmaxf(c1[3], SLOPE * c1[3]);
                msg[1][1][nbq][1] = fmaf(xv11, v, msg[1][1][nbq][1]);
            }
        }

        // ============ phase 3: msg -> smem (per-Nw copy), sum 4, atomics ============
        #pragma unroll
        for (int ch = 0; ch < 2; ch++)
            #pragma unroll
            for (int rh = 0; rh < 2; rh++)
                #pragma unroll
                for (int j = 0; j < 4; j++)
                    #pragma unroll
                    for (int d = 0; d < 2; d++) {
                        int row = Mw * 32 + ch * 16 + rh * 8 + (lane >> 2);
                        int o = (lane & 3) * 2 + 8 * j + d;
                        ms[row * 33 + o] = msg[ch][rh][j][d];
                    }
        __syncthreads();

        #pragma unroll 1
        for (int ee = 0; ee < 8; ee++) {
            int e2 = wid * 8 + ee;
            int dd = dreg[ee];
            if (dd >= 0) {
                float v = msb[e2 * 33 + lane]
                        + msb[128 * 33 + e2 * 33 + lane]
                        + msb[2 * 128 * 33 + e2 * 33 + lane]
                        + msb[3 * 128 * 33 + e2 * 33 + lane];
                atomicAdd(out + (size_t)dd * 32 + lane, v);
            }
        }
        // no tail barrier: atomic loop reads only msb + dreg; next tile's
        // msb writes are gated by the next phase-1 __syncthreads.
    }
}

// ---------------------------------------------------------------------------
extern "C" void kernel_launch(void* const* d_in, const int* in_sizes, int n_in,
                              void* d_out, int out_size)
{
    const float* x    = (const float*)d_in[0];
    const int*   ei   = (const int*)d_in[1];
    const float* ea   = (const float*)d_in[2];
    const float* W1   = (const float*)d_in[4];
    const float* b1   = (const float*)d_in[5];
    const float* g1   = (const float*)d_in[6];
    const float* be1  = (const float*)d_in[7];
    const float* m1   = (const float*)d_in[8];
    const float* v1   = (const float*)d_in[9];
    const float* W2   = (const float*)d_in[10];
    const float* b2   = (const float*)d_in[11];
    const float* g2   = (const float*)d_in[12];
    const float* be2  = (const float*)d_in[13];
    const float* m2   = (const float*)d_in[14];
    const float* v2   = (const float*)d_in[15];
    const float* root = (const float*)d_in[16];
    const float* bias = (const float*)d_in[17];
    float* out = (float*)d_out;

    cudaFuncSetAttribute(edge_kernel, cudaFuncAttributeMaxDynamicSharedMemorySize, SMEM_BYTES);

    fold_kernel<<<128, 256>>>(W1, b1, g1, be1, m1, v1, W2, b2, g2, be2, m2, v2, ei);
    init_kernel<<<(NN + 7) / 8, 256>>>(x, root, bias, out);
    edge_kernel<<<EGRID, 512, SMEM_BYTES>>>(x, ei, ea, out);
}

// round 14
// speedup vs baseline: 3.8083x; 1.0953x over previous
#include <cuda_runtime.h>
#include <cuda_fp16.h>
#include <cstdint>

#define NN 50000
#define NE 200000
#define EPSV 1e-5f
#define SLOPE 0.01f
#define NTILES 1563          // ceil(NE/128)
#define EGRID 148

#define BSTRIDE 80           // B tile row stride (64B data + 16 pad)
#define ASTRIDE 80           // A tile row stride (64B data + 16 pad)
#define MSTRIDE 36           // msg row stride in floats (16B-aligned rows)

// ---- dynamic smem byte offsets ----
#define OFF_BS   0           // B [1024 n][32 fp16]                 81920
#define OFF_AS   81920       // A [128 e][32 fp16]                  10240
#define OFF_XJ   92160       // xjT [32 i][128 e] float             16384
#define OFF_MSG  108544      // msg [4 Nw][128 e][36] float         73728
#define OFF_B2S  182272      // 1024 float
#define OFF_W1S  186368      // 512 float
#define OFF_B1S  188416      // 32 float
#define OFF_DST  188544      // 128 int
#define SMEM_BYTES 189056

// preprocessed weights
__device__ __half g_Bh[1024 * 32];   // [n][k] fp16(W2f[k][n] * bn-scale)
__device__ float g_b2f[1024];
__device__ float g_W1f[512];         // [d][k]
__device__ float g_b1f[32];
__device__ int   g_is64;

// ---------------- helpers ----------------
static __device__ __forceinline__ uint32_t smem_u32(const void* p) {
    uint32_t a;
    asm("{ .reg .u64 t; cvta.to.shared.u64 t, %1; cvt.u32.u64 %0, t; }" : "=r"(a) : "l"(p));
    return a;
}
static __device__ __forceinline__ void ldsm4(uint32_t r[4], uint32_t addr) {
    asm volatile("ldmatrix.sync.aligned.m8n8.x4.shared.b16 {%0,%1,%2,%3}, [%4];"
        : "=r"(r[0]), "=r"(r[1]), "=r"(r[2]), "=r"(r[3]) : "r"(addr));
}
static __device__ __forceinline__ void mma_f16(float c[4], const uint32_t a[4], const uint32_t* b) {
    asm volatile("mma.sync.aligned.m16n8k16.row.col.f32.f16.f16.f32 "
        "{%0,%1,%2,%3}, {%4,%5,%6,%7}, {%8,%9}, {%0,%1,%2,%3};"
        : "+f"(c[0]), "+f"(c[1]), "+f"(c[2]), "+f"(c[3])
        : "r"(a[0]), "r"(a[1]), "r"(a[2]), "r"(a[3]), "r"(b[0]), "r"(b[1]));
}
static __device__ __forceinline__ void red_v4(float* gptr, float4 v) {
    asm volatile("red.global.add.v4.f32 [%0], {%1, %2, %3, %4};"
        :: "l"(gptr), "f"(v.x), "f"(v.y), "f"(v.z), "f"(v.w) : "memory");
}

// prefetch next tile's scattered loads (indices + x row) into registers
static __device__ __forceinline__ void prefetch_tile(
    int t, int e, int qf, int is64,
    const int* __restrict__ ei32, const float* __restrict__ x,
    int& pdst, float4& px0, float4& px1)
{
    int eid = t * 128 + e;
    int valid = eid < NE;
    int eidc = valid ? eid : NE - 1;
    int src, dd;
    if (is64) { src = ei32[2 * eidc]; dd = ei32[2 * (NE + eidc)]; }
    else      { src = ei32[eidc];     dd = ei32[NE + eidc]; }
    pdst = valid ? dd : -1;
    const float4* xr = (const float4*)(x + (size_t)src * 32);
    px0 = xr[qf * 2];
    px1 = xr[qf * 2 + 1];
}

// ---------------------------------------------------------------------------
// fold: BN into weights; W2f -> single fp16.
// ---------------------------------------------------------------------------
__global__ void fold_kernel(const float* __restrict__ W1, const float* __restrict__ b1,
                            const float* __restrict__ g1, const float* __restrict__ be1,
                            const float* __restrict__ m1, const float* __restrict__ v1,
                            const float* __restrict__ W2, const float* __restrict__ b2,
                            const float* __restrict__ g2, const float* __restrict__ be2,
                            const float* __restrict__ m2, const float* __restrict__ v2,
                            const int* __restrict__ ei32)
{
    int idx = blockIdx.x * blockDim.x + threadIdx.x;   // 0..32767
    if (idx >= 32768) return;
    int n = idx & 1023;
    int k = idx >> 10;                                 // 0..31
    float s = g2[n] * rsqrtf(v2[n] + EPSV);
    g_Bh[n * 32 + k] = __float2half_rn(W2[k * 1024 + n] * s);
    if (k == 0) {
        g_b2f[n] = (b2[n] - m2[n]) * s + be2[n];
        if (n < 32) {
            float s1 = g1[n] * rsqrtf(v1[n] + EPSV);
            g_b1f[n] = (b1[n] - m1[n]) * s1 + be1[n];
            #pragma unroll
            for (int d = 0; d < 16; d++)
                g_W1f[d * 32 + n] = W1[d * 32 + n] * s1;
        }
        if (n == 0) {
            int all0 = 1;
            for (int i = 0; i < 64; i++)
                if (ei32[2 * i + 1] != 0) { all0 = 0; break; }
            g_is64 = all0;
        }
    }
}

// ---------------------------------------------------------------------------
// out[n,:] = bias + x[n,:] @ root
// ---------------------------------------------------------------------------
__global__ void init_kernel(const float* __restrict__ x,
                            const float* __restrict__ root,
                            const float* __restrict__ bias,
                            float* __restrict__ out)
{
    __shared__ float root_s[1024];
    __shared__ float bias_s[32];
    int t = threadIdx.x;
    for (int i = t; i < 1024; i += blockDim.x) root_s[i] = root[i];
    if (t < 32) bias_s[t] = bias[t];
    __syncthreads();
    int lane = t & 31, w = t >> 5;
    int n = blockIdx.x * (blockDim.x >> 5) + w;
    if (n >= NN) return;
    float xv = x[n * 32 + lane];
    float acc = bias_s[lane];
    #pragma unroll
    for (int i = 0; i < 32; i++)
        acc = fmaf(__shfl_sync(0xffffffffu, xv, i), root_s[i * 32 + lane], acc);
    out[n * 32 + lane] = acc;
}

// ---------------------------------------------------------------------------
// Persistent fused edge kernel: 512 thr, fp16 mma.sync + red.v4 scatter.
// ---------------------------------------------------------------------------
extern __shared__ char smem[];

__global__ void __launch_bounds__(512, 1)
edge_kernel(const float* __restrict__ x,
            const int*   __restrict__ ei32,
            const float* __restrict__ edge_attr,
            float* __restrict__ out)
{
    const int tid = threadIdx.x;
    const int lane = tid & 31, wid = tid >> 5;
    const int Mw = wid & 3, Nw = wid >> 2;              // 4 M-warps x 4 N-warps
    uint32_t su = smem_u32(smem);

    // ---- persistent copies: B, b2f, W1f, b1f ----
    {
        const int4* bs = (const int4*)g_Bh;
        for (int i = tid; i < 4096; i += 512) {        // 1024 rows x 4 int4
            int n = i >> 2, seg = i & 3;
            *(int4*)(smem + OFF_BS + n * BSTRIDE + seg * 16) = bs[i];
        }
        float* b2w = (float*)(smem + OFF_B2S);
        for (int i = tid; i < 1024; i += 512) b2w[i] = g_b2f[i];
        float* w1w = (float*)(smem + OFF_W1S);
        if (tid < 512) w1w[tid] = g_W1f[tid];
        if (tid < 32) ((float*)(smem + OFF_B1S))[tid] = g_b1f[tid];
    }
    const int is64 = g_is64;
    __syncthreads();

    // ldmatrix base addresses
    uint32_t a_base = su + OFF_AS + (uint32_t)(Mw * 32 + (lane & 15)) * ASTRIDE + (lane >> 4) * 16;
    // B ldsm4: lane&7 = row, lane>>3 = 16B chunk (k0-7|k8-15|k16-23|k24-31)
    uint32_t b_base = su + OFF_BS + (uint32_t)(Nw * 256 + (lane & 7)) * BSTRIDE + (lane >> 3) * 16;

    const float* b2s = (const float*)(smem + OFF_B2S);
    const float* xj  = (const float*)(smem + OFF_XJ);
    float* ms        = (float*)(smem + OFF_MSG) + Nw * (128 * MSTRIDE);
    const float* msb = (const float*)(smem + OFF_MSG);
    int* dst_s       = (int*)(smem + OFF_DST);

    const int e  = tid >> 2;      // edge within tile (4 threads per edge)
    const int qf = tid & 3;       // quarter: k-range [qf*8, qf*8+8)
    const int e3 = wid * 8 + (lane >> 2);   // phase-3 edge (one per 4 lanes)
    const int q3 = lane & 3;                // phase-3 o-quarter: [8*q3, 8*q3+8)

    int pf_dst; float4 px0, px1;
    int tile = blockIdx.x;
    if (tile < NTILES)
        prefetch_tile(tile, e, qf, is64, ei32, x, pf_dst, px0, px1);

    for (; tile < NTILES; tile += gridDim.x) {
        // ============ phase 1 (compute-only; scattered data prefetched) ============
        {
            if (qf == 0) dst_s[e] = pf_dst;

            // xjT stores from prefetched x row
            float* xjw = (float*)(smem + OFF_XJ);
            int i0 = qf * 8;
            xjw[(i0 + 0) * 128 + e] = px0.x;
            xjw[(i0 + 1) * 128 + e] = px0.y;
            xjw[(i0 + 2) * 128 + e] = px0.z;
            xjw[(i0 + 3) * 128 + e] = px0.w;
            xjw[(i0 + 4) * 128 + e] = px1.x;
            xjw[(i0 + 5) * 128 + e] = px1.y;
            xjw[(i0 + 6) * 128 + e] = px1.z;
            xjw[(i0 + 7) * 128 + e] = px1.w;

            // edge_attr load (sequential, L2-friendly)
            int eidc = tile * 128 + e;
            if (eidc >= NE) eidc = NE - 1;
            const float4* er = (const float4*)(edge_attr + (size_t)eidc * 16);
            float4 q0 = er[0], q1 = er[1], q2 = er[2], q3v = er[3];
            float eav[16] = {q0.x,q0.y,q0.z,q0.w, q1.x,q1.y,q1.z,q1.w,
                             q2.x,q2.y,q2.z,q2.w, q3v.x,q3v.y,q3v.z,q3v.w};

            // layer 1: this thread's 8 k-values
            float hval[8];
            const float* W1s = (const float*)(smem + OFF_W1S) + qf * 8;
            const float* b1s = (const float*)(smem + OFF_B1S) + qf * 8;
            #pragma unroll
            for (int k = 0; k < 8; k++) hval[k] = b1s[k];
            #pragma unroll
            for (int d = 0; d < 16; d++) {
                float a = eav[d];
                #pragma unroll
                for (int k = 0; k < 8; k++)
                    hval[k] = fmaf(a, W1s[d * 32 + k], hval[k]);
            }
            #pragma unroll
            for (int k = 0; k < 8; k++) hval[k] = fmaxf(hval[k], SLOPE * hval[k]);

            // A row segment: 8 fp16 = 16 bytes at offset qf*16
            union { __half2 h2[4]; uint4 u4; } pk;
            #pragma unroll
            for (int j = 0; j < 4; j++)
                pk.h2[j] = __halves2half2(__float2half_rn(hval[2 * j]),
                                          __float2half_rn(hval[2 * j + 1]));
            *(uint4*)(smem + OFF_AS + e * ASTRIDE + qf * 16) = pk.u4;
        }
        __syncthreads();

        // ============ phase 2: A-frags, dst->reg, prefetch, MMA + epilogue ============
        uint32_t af[2][2][4];   // [row-chunk][k-half]
        #pragma unroll
        for (int c = 0; c < 2; c++) {
            ldsm4(af[c][0], a_base + c * (16 * ASTRIDE));
            ldsm4(af[c][1], a_base + c * (16 * ASTRIDE) + 32);
        }

        // this thread's phase-3 dst -> register (frees the tail barrier)
        const int dd3 = dst_s[e3];

        int nt = tile + gridDim.x;
        if (nt < NTILES)
            prefetch_tile(nt, e, qf, is64, ei32, x, pf_dst, px0, px1);

        const int r0 = Mw * 32 + (lane >> 2);

        float msg[2][2][4][2];
        #pragma unroll
        for (int a1 = 0; a1 < 2; a1++)
            #pragma unroll
            for (int a2 = 0; a2 < 2; a2++)
                #pragma unroll
                for (int a3 = 0; a3 < 4; a3++)
                    { msg[a1][a2][a3][0] = 0.f; msg[a1][a2][a3][1] = 0.f; }

        #pragma unroll 2
        for (int nbo = 0; nbo < 8; nbo++) {
            // ii fixed for the 4 nb in this group: hoist xv loads
            int ii = Nw * 8 + nbo;
            float xv00 = xj[ii * 128 + r0];
            float xv01 = xj[ii * 128 + r0 + 8];
            float xv10 = xj[ii * 128 + r0 + 16];
            float xv11 = xj[ii * 128 + r0 + 24];

            #pragma unroll
            for (int nbq = 0; nbq < 4; nbq++) {
                int nb = nbo * 4 + nbq;
                int n0 = Nw * 256 + nb * 8;
                uint32_t gg[4];                         // g0 = gg[0..1], g1 = gg[2..3]
                ldsm4(gg, b_base + (uint32_t)(nb * 8) * BSTRIDE);
                float2 b2v = *(const float2*)(b2s + n0 + (lane & 3) * 2);

                // bias folded into accumulator init
                float c0[4] = {b2v.x, b2v.y, b2v.x, b2v.y};
                float c1[4] = {b2v.x, b2v.y, b2v.x, b2v.y};
                mma_f16(c0, af[0][0], gg);      mma_f16(c1, af[1][0], gg);
                mma_f16(c0, af[0][1], gg + 2);  mma_f16(c1, af[1][1], gg + 2);

                float v;
                v = fmaxf(c0[0], SLOPE * c0[0]);
                msg[0][0][nbq][0] = fmaf(xv00, v, msg[0][0][nbq][0]);
                v = fmaxf(c0[1], SLOPE * c0[1]);
                msg[0][0][nbq][1] = fmaf(xv00, v, msg[0][0][nbq][1]);
                v = fmaxf(c0[2], SLOPE * c0[2]);
                msg[0][1][nbq][0] = fmaf(xv01, v, msg[0][1][nbq][0]);
                v = fmaxf(c0[3], SLOPE * c0[3]);
                msg[0][1][nbq][1] = fmaf(xv01, v, msg[0][1][nbq][1]);
                v = fmaxf(c1[0], SLOPE * c1[0]);
                msg[1][0][nbq][0] = fmaf(xv10, v, msg[1][0][nbq][0]);
                v = fmaxf(c1[1], SLOPE * c1[1]);
                msg[1][0][nbq][1] = fmaf(xv10, v, msg[1][0][nbq][1]);
                v = fmaxf(c1[2], SLOPE * c1[2]);
                msg[1][1][nbq][0] = fmaf(xv11, v, msg[1][1][nbq][0]);
                v = fmaxf(c1[3], SLOPE * c1[3]);
                msg[1][1][nbq][1] = fmaf(xv11, v, msg[1][1][nbq][1]);
            }
        }

        // ============ phase 3: msg -> smem, sum 4 copies, red.v4 scatter ============
        #pragma unroll
        for (int ch = 0; ch < 2; ch++)
            #pragma unroll
            for (int rh = 0; rh < 2; rh++)
                #pragma unroll
                for (int j = 0; j < 4; j++)
                    #pragma unroll
                    for (int d = 0; d < 2; d++) {
                        int row = Mw * 32 + ch * 16 + rh * 8 + (lane >> 2);
                        int o = (lane & 3) * 2 + 8 * j + d;
                        ms[row * MSTRIDE + o] = msg[ch][rh][j][d];
                    }
        __syncthreads();

        if (dd3 >= 0) {
            const float4* p0 = (const float4*)(msb + e3 * MSTRIDE + 8 * q3);
            const float4* p1 = (const float4*)(msb + 128 * MSTRIDE + e3 * MSTRIDE + 8 * q3);
            const float4* p2 = (const float4*)(msb + 2 * 128 * MSTRIDE + e3 * MSTRIDE + 8 * q3);
            const float4* p3 = (const float4*)(msb + 3 * 128 * MSTRIDE + e3 * MSTRIDE + 8 * q3);
            float4 a0 = p0[0], b0 = p1[0], c0 = p2[0], d0 = p3[0];
            float4 a1 = p0[1], b1 = p1[1], c1 = p2[1], d1 = p3[1];
            float4 s0 = make_float4(a0.x + b0.x + c0.x + d0.x,
                                    a0.y + b0.y + c0.y + d0.y,
                                    a0.z + b0.z + c0.z + d0.z,
                                    a0.w + b0.w + c0.w + d0.w);
            float4 s1 = make_float4(a1.x + b1.x + c1.x + d1.x,
                                    a1.y + b1.y + c1.y + d1.y,
                                    a1.z + b1.z + c1.z + d1.z,
                                    a1.w + b1.w + c1.w + d1.w);
            float* gp = out + (size_t)dd3 * 32 + 8 * q3;
            red_v4(gp, s0);
            red_v4(gp + 4, s1);
        }
        // no tail barrier: phase-3 reads only msb (+dd3 in reg); next tile's
        // msb writes are gated by the next phase-1 __syncthreads.
    }
}

// ---------------------------------------------------------------------------
extern "C" void kernel_launch(void* const* d_in, const int* in_sizes, int n_in,
                              void* d_out, int out_size)
{
    const float* x    = (const float*)d_in[0];
    const int*   ei   = (const int*)d_in[1];
    const float* ea   = (const float*)d_in[2];
    const float* W1   = (const float*)d_in[4];
    const float* b1   = (const float*)d_in[5];
    const float* g1   = (const float*)d_in[6];
    const float* be1  = (const float*)d_in[7];
    const float* m1   = (const float*)d_in[8];
    const float* v1   = (const float*)d_in[9];
    const float* W2   = (const float*)d_in[10];
    const float* b2   = (const float*)d_in[11];
    const float* g2   = (const float*)d_in[12];
    const float* be2  = (const float*)d_in[13];
    const float* m2   = (const float*)d_in[14];
    const float* v2   = (const float*)d_in[15];
    const float* root = (const float*)d_in[16];
    const float* bias = (const float*)d_in[17];
    float* out = (float*)d_out;

    cudaFuncSetAttribute(edge_kernel, cudaFuncAttributeMaxDynamicSharedMemorySize, SMEM_BYTES);

    fold_kernel<<<128, 256>>>(W1, b1, g1, be1, m1, v1, W2, b2, g2, be2, m2, v2, ei);
    init_kernel<<<(NN + 7) / 8, 256>>>(x, root, bias, out);
    edge_kernel<<<EGRID, 512, SMEM_BYTES>>>(x, ei, ea, out);
}

// round 15
// speedup vs baseline: 3.8912x; 1.0218x over previous
#include <cuda_runtime.h>
#include <cuda_fp16.h>
#include <cstdint>

#define NN 50000
#define NE 200000
#define EPSV 1e-5f
#define SLOPE 0.01f
#define NTILES 1563          // ceil(NE/128)
#define EGRID 148

#define BSTRIDE 80           // B tile row stride (64B data + 16 pad)
#define ASTRIDE 80           // A tile row stride (64B data + 16 pad)
#define MSTRIDE 36           // msg row stride in floats (16B-aligned rows)

// ---- dynamic smem byte offsets ----
#define OFF_BS   0           // B [1024 n][32 fp16]                 81920
#define OFF_AS   81920       // A [128 e][32 fp16]                  10240
#define OFF_XJ   92160       // xjT [32 i][128 e] float             16384
#define OFF_MSG  108544      // msg [4 Nw][128 e][36] float         73728
#define OFF_B2S  182272      // 1024 float
#define OFF_W1S  186368      // 512 float
#define OFF_B1S  188416      // 32 float
#define OFF_DST  188544      // 128 int
#define SMEM_BYTES 189056

// prep_kernel grid split
#define FOLD_BLOCKS 128
#define INIT_BLOCKS ((NN + 7) / 8)          // 6250 (8 nodes per 256-thr block)

// preprocessed weights
__device__ __half g_Bh[1024 * 32];   // [n][k] fp16(W2f[k][n] * bn-scale)
__device__ float g_b2f[1024];
__device__ float g_W1f[512];         // [d][k]
__device__ float g_b1f[32];
__device__ int   g_is64;

// ---------------- helpers ----------------
static __device__ __forceinline__ uint32_t smem_u32(const void* p) {
    uint32_t a;
    asm("{ .reg .u64 t; cvta.to.shared.u64 t, %1; cvt.u32.u64 %0, t; }" : "=r"(a) : "l"(p));
    return a;
}
static __device__ __forceinline__ void ldsm4(uint32_t r[4], uint32_t addr) {
    asm volatile("ldmatrix.sync.aligned.m8n8.x4.shared.b16 {%0,%1,%2,%3}, [%4];"
        : "=r"(r[0]), "=r"(r[1]), "=r"(r[2]), "=r"(r[3]) : "r"(addr));
}
static __device__ __forceinline__ void mma_f16(float c[4], const uint32_t a[4], const uint32_t* b) {
    asm volatile("mma.sync.aligned.m16n8k16.row.col.f32.f16.f16.f32 "
        "{%0,%1,%2,%3}, {%4,%5,%6,%7}, {%8,%9}, {%0,%1,%2,%3};"
        : "+f"(c[0]), "+f"(c[1]), "+f"(c[2]), "+f"(c[3])
        : "r"(a[0]), "r"(a[1]), "r"(a[2]), "r"(a[3]), "r"(b[0]), "r"(b[1]));
}
static __device__ __forceinline__ void red_v4(float* gptr, float4 v) {
    asm volatile("red.global.add.v4.f32 [%0], {%1, %2, %3, %4};"
        :: "l"(gptr), "f"(v.x), "f"(v.y), "f"(v.z), "f"(v.w) : "memory");
}

// prefetch next tile's scattered loads (indices + x row) into registers
static __device__ __forceinline__ void prefetch_tile(
    int t, int e, int qf, int is64,
    const int* __restrict__ ei32, const float* __restrict__ x,
    int& pdst, float4& px0, float4& px1)
{
    int eid = t * 128 + e;
    int valid = eid < NE;
    int eidc = valid ? eid : NE - 1;
    int src, dd;
    if (is64) { src = ei32[2 * eidc]; dd = ei32[2 * (NE + eidc)]; }
    else      { src = ei32[eidc];     dd = ei32[NE + eidc]; }
    pdst = valid ? dd : -1;
    const float4* xr = (const float4*)(x + (size_t)src * 32);
    px0 = xr[qf * 2];
    px1 = xr[qf * 2 + 1];
}

// ---------------------------------------------------------------------------
// prep: fused fold (blocks 0..127) + init (blocks 128..).
//   fold: BN into weights; W2f -> single fp16; detect edge_index dtype.
//   init: out[n,:] = bias + x[n,:] @ root
// Independent workloads -> overlap fold's latency with init's bandwidth.
// ---------------------------------------------------------------------------
__global__ void __launch_bounds__(256)
prep_kernel(const float* __restrict__ W1, const float* __restrict__ b1,
            const float* __restrict__ g1, const float* __restrict__ be1,
            const float* __restrict__ m1, const float* __restrict__ v1,
            const float* __restrict__ W2, const float* __restrict__ b2,
            const float* __restrict__ g2, const float* __restrict__ be2,
            const float* __restrict__ m2, const float* __restrict__ v2,
            const int* __restrict__ ei32,
            const float* __restrict__ x,
            const float* __restrict__ root,
            const float* __restrict__ bias,
            float* __restrict__ out)
{
    if (blockIdx.x < FOLD_BLOCKS) {
        // ---------------- fold ----------------
        int idx = blockIdx.x * 256 + threadIdx.x;      // 0..32767
        int n = idx & 1023;
        int k = idx >> 10;                             // 0..31
        float s = g2[n] * rsqrtf(v2[n] + EPSV);
        g_Bh[n * 32 + k] = __float2half_rn(W2[k * 1024 + n] * s);
        if (k == 0) {
            g_b2f[n] = (b2[n] - m2[n]) * s + be2[n];
            if (n < 32) {
                float s1 = g1[n] * rsqrtf(v1[n] + EPSV);
                g_b1f[n] = (b1[n] - m1[n]) * s1 + be1[n];
                #pragma unroll
                for (int d = 0; d < 16; d++)
                    g_W1f[d * 32 + n] = W1[d * 32 + n] * s1;
            }
            if (n == 0) {
                int all0 = 1;
                for (int i = 0; i < 64; i++)
                    if (ei32[2 * i + 1] != 0) { all0 = 0; break; }
                g_is64 = all0;
            }
        }
        return;
    }

    // ---------------- init ----------------
    __shared__ float root_s[1024];
    __shared__ float bias_s[32];
    int t = threadIdx.x;
    for (int i = t; i < 1024; i += 256) root_s[i] = root[i];
    if (t < 32) bias_s[t] = bias[t];
    __syncthreads();
    int lane = t & 31, w = t >> 5;
    int n = (blockIdx.x - FOLD_BLOCKS) * 8 + w;
    if (n >= NN) return;
    float xv = x[n * 32 + lane];
    float acc = bias_s[lane];
    #pragma unroll
    for (int i = 0; i < 32; i++)
        acc = fmaf(__shfl_sync(0xffffffffu, xv, i), root_s[i * 32 + lane], acc);
    out[n * 32 + lane] = acc;
}

// ---------------------------------------------------------------------------
// Persistent fused edge kernel: 512 thr, fp16 mma.sync + red.v4 scatter.
// ---------------------------------------------------------------------------
extern __shared__ char smem[];

__global__ void __launch_bounds__(512, 1)
edge_kernel(const float* __restrict__ x,
            const int*   __restrict__ ei32,
            const float* __restrict__ edge_attr,
            float* __restrict__ out)
{
    const int tid = threadIdx.x;
    const int lane = tid & 31, wid = tid >> 5;
    const int Mw = wid & 3, Nw = wid >> 2;              // 4 M-warps x 4 N-warps
    uint32_t su = smem_u32(smem);

    // ---- persistent copies: B, b2f, W1f, b1f ----
    {
        const int4* bs = (const int4*)g_Bh;
        for (int i = tid; i < 4096; i += 512) {        // 1024 rows x 4 int4
            int n = i >> 2, seg = i & 3;
            *(int4*)(smem + OFF_BS + n * BSTRIDE + seg * 16) = bs[i];
        }
        float* b2w = (float*)(smem + OFF_B2S);
        for (int i = tid; i < 1024; i += 512) b2w[i] = g_b2f[i];
        float* w1w = (float*)(smem + OFF_W1S);
        if (tid < 512) w1w[tid] = g_W1f[tid];
        if (tid < 32) ((float*)(smem + OFF_B1S))[tid] = g_b1f[tid];
    }
    const int is64 = g_is64;
    __syncthreads();

    // ldmatrix base addresses
    uint32_t a_base = su + OFF_AS + (uint32_t)(Mw * 32 + (lane & 15)) * ASTRIDE + (lane >> 4) * 16;
    // B ldsm4: lane&7 = row, lane>>3 = 16B chunk (k0-7|k8-15|k16-23|k24-31)
    uint32_t b_base = su + OFF_BS + (uint32_t)(Nw * 256 + (lane & 7)) * BSTRIDE + (lane >> 3) * 16;

    const float* b2s = (const float*)(smem + OFF_B2S);
    const float* xj  = (const float*)(smem + OFF_XJ);
    float* ms        = (float*)(smem + OFF_MSG) + Nw * (128 * MSTRIDE);
    const float* msb = (const float*)(smem + OFF_MSG);
    int* dst_s       = (int*)(smem + OFF_DST);

    const int e  = tid >> 2;      // edge within tile (4 threads per edge)
    const int qf = tid & 3;       // quarter: k-range [qf*8, qf*8+8)
    const int e3 = wid * 8 + (lane >> 2);   // phase-3 edge (one per 4 lanes)
    const int q3 = lane & 3;                // phase-3 o-quarter: [8*q3, 8*q3+8)

    int pf_dst; float4 px0, px1;
    int tile = blockIdx.x;
    if (tile < NTILES)
        prefetch_tile(tile, e, qf, is64, ei32, x, pf_dst, px0, px1);

    for (; tile < NTILES; tile += gridDim.x) {
        // ============ phase 1 (compute-only; scattered data prefetched) ============
        {
            if (qf == 0) dst_s[e] = pf_dst;

            // xjT stores from prefetched x row
            float* xjw = (float*)(smem + OFF_XJ);
            int i0 = qf * 8;
            xjw[(i0 + 0) * 128 + e] = px0.x;
            xjw[(i0 + 1) * 128 + e] = px0.y;
            xjw[(i0 + 2) * 128 + e] = px0.z;
            xjw[(i0 + 3) * 128 + e] = px0.w;
            xjw[(i0 + 4) * 128 + e] = px1.x;
            xjw[(i0 + 5) * 128 + e] = px1.y;
            xjw[(i0 + 6) * 128 + e] = px1.z;
            xjw[(i0 + 7) * 128 + e] = px1.w;

            // edge_attr load (sequential, L2-friendly)
            int eidc = tile * 128 + e;
            if (eidc >= NE) eidc = NE - 1;
            const float4* er = (const float4*)(edge_attr + (size_t)eidc * 16);
            float4 q0 = er[0], q1 = er[1], q2 = er[2], q3v = er[3];
            float eav[16] = {q0.x,q0.y,q0.z,q0.w, q1.x,q1.y,q1.z,q1.w,
                             q2.x,q2.y,q2.z,q2.w, q3v.x,q3v.y,q3v.z,q3v.w};

            // layer 1: this thread's 8 k-values
            float hval[8];
            const float* W1s = (const float*)(smem + OFF_W1S) + qf * 8;
            const float* b1s = (const float*)(smem + OFF_B1S) + qf * 8;
            #pragma unroll
            for (int k = 0; k < 8; k++) hval[k] = b1s[k];
            #pragma unroll
            for (int d = 0; d < 16; d++) {
                float a = eav[d];
                #pragma unroll
                for (int k = 0; k < 8; k++)
                    hval[k] = fmaf(a, W1s[d * 32 + k], hval[k]);
            }
            #pragma unroll
            for (int k = 0; k < 8; k++) hval[k] = fmaxf(hval[k], SLOPE * hval[k]);

            // A row segment: 8 fp16 = 16 bytes at offset qf*16
            union { __half2 h2[4]; uint4 u4; } pk;
            #pragma unroll
            for (int j = 0; j < 4; j++)
                pk.h2[j] = __halves2half2(__float2half_rn(hval[2 * j]),
                                          __float2half_rn(hval[2 * j + 1]));
            *(uint4*)(smem + OFF_AS + e * ASTRIDE + qf * 16) = pk.u4;
        }
        __syncthreads();

        // ============ phase 2: A-frags, dst->reg, prefetch, MMA + epilogue ============
        uint32_t af[2][2][4];   // [row-chunk][k-half]
        #pragma unroll
        for (int c = 0; c < 2; c++) {
            ldsm4(af[c][0], a_base + c * (16 * ASTRIDE));
            ldsm4(af[c][1], a_base + c * (16 * ASTRIDE) + 32);
        }

        // this thread's phase-3 dst -> register (frees the tail barrier)
        const int dd3 = dst_s[e3];

        int nt = tile + gridDim.x;
        if (nt < NTILES)
            prefetch_tile(nt, e, qf, is64, ei32, x, pf_dst, px0, px1);

        const int r0 = Mw * 32 + (lane >> 2);

        float msg[2][2][4][2];
        #pragma unroll
        for (int a1 = 0; a1 < 2; a1++)
            #pragma unroll
            for (int a2 = 0; a2 < 2; a2++)
                #pragma unroll
                for (int a3 = 0; a3 < 4; a3++)
                    { msg[a1][a2][a3][0] = 0.f; msg[a1][a2][a3][1] = 0.f; }

        #pragma unroll 2
        for (int nbo = 0; nbo < 8; nbo++) {
            // ii fixed for the 4 nb in this group: hoist xv loads
            int ii = Nw * 8 + nbo;
            float xv00 = xj[ii * 128 + r0];
            float xv01 = xj[ii * 128 + r0 + 8];
            float xv10 = xj[ii * 128 + r0 + 16];
            float xv11 = xj[ii * 128 + r0 + 24];

            #pragma unroll
            for (int nbq = 0; nbq < 4; nbq++) {
                int nb = nbo * 4 + nbq;
                int n0 = Nw * 256 + nb * 8;
                uint32_t gg[4];                         // g0 = gg[0..1], g1 = gg[2..3]
                ldsm4(gg, b_base + (uint32_t)(nb * 8) * BSTRIDE);
                float2 b2v = *(const float2*)(b2s + n0 + (lane & 3) * 2);

                // bias folded into accumulator init
                float c0[4] = {b2v.x, b2v.y, b2v.x, b2v.y};
                float c1[4] = {b2v.x, b2v.y, b2v.x, b2v.y};
                mma_f16(c0, af[0][0], gg);      mma_f16(c1, af[1][0], gg);
                mma_f16(c0, af[0][1], gg + 2);  mma_f16(c1, af[1][1], gg + 2);

                float v;
                v = fmaxf(c0[0], SLOPE * c0[0]);
                msg[0][0][nbq][0] = fmaf(xv00, v, msg[0][0][nbq][0]);
                v = fmaxf(c0[1], SLOPE * c0[1]);
                msg[0][0][nbq][1] = fmaf(xv00, v, msg[0][0][nbq][1]);
                v = fmaxf(c0[2], SLOPE * c0[2]);
                msg[0][1][nbq][0] = fmaf(xv01, v, msg[0][1][nbq][0]);
                v = fmaxf(c0[3], SLOPE * c0[3]);
                msg[0][1][nbq][1] = fmaf(xv01, v, msg[0][1][nbq][1]);
                v = fmaxf(c1[0], SLOPE * c1[0]);
                msg[1][0][nbq][0] = fmaf(xv10, v, msg[1][0][nbq][0]);
                v = fmaxf(c1[1], SLOPE * c1[1]);
                msg[1][0][nbq][1] = fmaf(xv10, v, msg[1][0][nbq][1]);
                v = fmaxf(c1[2], SLOPE * c1[2]);
                msg[1][1][nbq][0] = fmaf(xv11, v, msg[1][1][nbq][0]);
                v = fmaxf(c1[3], SLOPE * c1[3]);
                msg[1][1][nbq][1] = fmaf(xv11, v, msg[1][1][nbq][1]);
            }
        }

        // ============ phase 3: msg -> smem, sum 4 copies, red.v4 scatter ============
        #pragma unroll
        for (int ch = 0; ch < 2; ch++)
            #pragma unroll
            for (int rh = 0; rh < 2; rh++)
                #pragma unroll
                for (int j = 0; j < 4; j++)
                    #pragma unroll
                    for (int d = 0; d < 2; d++) {
                        int row = Mw * 32 + ch * 16 + rh * 8 + (lane >> 2);
                        int o = (lane & 3) * 2 + 8 * j + d;
                        ms[row * MSTRIDE + o] = msg[ch][rh][j][d];
                    }
        __syncthreads();

        if (dd3 >= 0) {
            const float4* p0 = (const float4*)(msb + e3 * MSTRIDE + 8 * q3);
            const float4* p1 = (const float4*)(msb + 128 * MSTRIDE + e3 * MSTRIDE + 8 * q3);
            const float4* p2 = (const float4*)(msb + 2 * 128 * MSTRIDE + e3 * MSTRIDE + 8 * q3);
            const float4* p3 = (const float4*)(msb + 3 * 128 * MSTRIDE + e3 * MSTRIDE + 8 * q3);
            float4 a0 = p0[0], b0 = p1[0], c0 = p2[0], d0 = p3[0];
            float4 a1 = p0[1], b1 = p1[1], c1 = p2[1], d1 = p3[1];
            float4 s0 = make_float4(a0.x + b0.x + c0.x + d0.x,
                                    a0.y + b0.y + c0.y + d0.y,
                                    a0.z + b0.z + c0.z + d0.z,
                                    a0.w + b0.w + c0.w + d0.w);
            float4 s1 = make_float4(a1.x + b1.x + c1.x + d1.x,
                                    a1.y + b1.y + c1.y + d1.y,
                                    a1.z + b1.z + c1.z + d1.z,
                                    a1.w + b1.w + c1.w + d1.w);
            float* gp = out + (size_t)dd3 * 32 + 8 * q3;
            red_v4(gp, s0);
            red_v4(gp + 4, s1);
        }
        // no tail barrier: phase-3 reads only msb (+dd3 in reg); next tile's
        // msb writes are gated by the next phase-1 __syncthreads.
    }
}

// ---------------------------------------------------------------------------
extern "C" void kernel_launch(void* const* d_in, const int* in_sizes, int n_in,
                              void* d_out, int out_size)
{
    const float* x    = (const float*)d_in[0];
    const int*   ei   = (const int*)d_in[1];
    const float* ea   = (const float*)d_in[2];
    const float* W1   = (const float*)d_in[4];
    const float* b1   = (const float*)d_in[5];
    const float* g1   = (const float*)d_in[6];
    const float* be1  = (const float*)d_in[7];
    const float* m1   = (const float*)d_in[8];
    const float* v1   = (const float*)d_in[9];
    const float* W2   = (const float*)d_in[10];
    const float* b2   = (const float*)d_in[11];
    const float* g2   = (const float*)d_in[12];
    const float* be2  = (const float*)d_in[13];
    const float* m2   = (const float*)d_in[14];
    const float* v2   = (const float*)d_in[15];
    const float* root = (const float*)d_in[16];
    const float* bias = (const float*)d_in[17];
    float* out = (float*)d_out;

    cudaFuncSetAttribute(edge_kernel, cudaFuncAttributeMaxDynamicSharedMemorySize, SMEM_BYTES);

    prep_kernel<<<FOLD_BLOCKS + INIT_BLOCKS, 256>>>(
        W1, b1, g1, be1, m1, v1, W2, b2, g2, be2, m2, v2, ei,
        x, root, bias, out);
    edge_kernel<<<EGRID, 512, SMEM_BYTES>>>(x, ei, ea, out);
}

// round 17
// speedup vs baseline: 4.2192x; 1.0843x over previous
#include <cuda_runtime.h>
#include <cuda_fp16.h>
#include <cstdint>

#define NN 50000
#define NE 200000
#define EPSV 1e-5f
#define SLOPE 0.01f
#define NTILES 1563          // ceil(NE/128)
#define EGRID 296            // 2 persistent CTAs per SM

#define BSTRIDE 80           // B tile row stride (64B data + 16 pad)
#define ASTRIDE 80           // A tile row stride (64B data + 16 pad)
#define XSTRIDE 80           // xj fp16 row stride BYTES (16B multiple!)
#define MSTRIDE 36           // msg row stride floats

// ---- dynamic smem byte offsets ----
#define OFF_BS   0           // B [1024 n][32 fp16]                 81920
#define OFF_AS   81920       // A [128 e][32 fp16]                  10240
#define OFF_XJ   92160       // xj fp16 [128 e][32 i] pad           10240
#define OFF_MSG  81920       // msg [128 e][36] float (OVERLAYS A+XJ, 18432 <= 20480)
#define OFF_B2S  102400      // 1024 float
#define OFF_W1S  106496      // 512 float
#define OFF_B1S  108544      // 32 float
#define OFF_DST  108672      // 128 int
#define SMEM_BYTES 109184    // x2 CTAs = 218.4KB <= 228KB/SM

// prep_kernel grid split
#define FOLD_BLOCKS 128
#define INIT_BLOCKS ((NN + 7) / 8)

// preprocessed weights
__device__ __half g_Bh[1024 * 32];   // [n][k] fp16(W2f[k][n] * bn-scale)
__device__ float g_b2f[1024];
__device__ float g_W1f[512];         // [d][k]
__device__ float g_b1f[32];
__device__ int   g_is64;

// ---------------- helpers ----------------
static __device__ __forceinline__ uint32_t smem_u32(const void* p) {
    uint32_t a;
    asm("{ .reg .u64 t; cvta.to.shared.u64 t, %1; cvt.u32.u64 %0, t; }" : "=r"(a) : "l"(p));
    return a;
}
static __device__ __forceinline__ void ldsm4(uint32_t r[4], uint32_t addr) {
    asm volatile("ldmatrix.sync.aligned.m8n8.x4.shared.b16 {%0,%1,%2,%3}, [%4];"
        : "=r"(r[0]), "=r"(r[1]), "=r"(r[2]), "=r"(r[3]) : "r"(addr));
}
static __device__ __forceinline__ void mma_f16(float c[4], const uint32_t a[4], const uint32_t* b) {
    asm volatile("mma.sync.aligned.m16n8k16.row.col.f32.f16.f16.f32 "
        "{%0,%1,%2,%3}, {%4,%5,%6,%7}, {%8,%9}, {%0,%1,%2,%3};"
        : "+f"(c[0]), "+f"(c[1]), "+f"(c[2]), "+f"(c[3])
        : "r"(a[0]), "r"(a[1]), "r"(a[2]), "r"(a[3]), "r"(b[0]), "r"(b[1]));
}
static __device__ __forceinline__ void red_v4(float* gptr, float4 v) {
    asm volatile("red.global.add.v4.f32 [%0], {%1, %2, %3, %4};"
        :: "l"(gptr), "f"(v.x), "f"(v.y), "f"(v.z), "f"(v.w) : "memory");
}

// ---------------------------------------------------------------------------
// prep: fused fold (blocks 0..127) + init (blocks 128..).
// ---------------------------------------------------------------------------
__global__ void __launch_bounds__(256)
prep_kernel(const float* __restrict__ W1, const float* __restrict__ b1,
            const float* __restrict__ g1, const float* __restrict__ be1,
            const float* __restrict__ m1, const float* __restrict__ v1,
            const float* __restrict__ W2, const float* __restrict__ b2,
            const float* __restrict__ g2, const float* __restrict__ be2,
            const float* __restrict__ m2, const float* __restrict__ v2,
            const int* __restrict__ ei32,
            const float* __restrict__ x,
            const float* __restrict__ root,
            const float* __restrict__ bias,
            float* __restrict__ out)
{
    if (blockIdx.x < FOLD_BLOCKS) {
        int idx = blockIdx.x * 256 + threadIdx.x;      // 0..32767
        int n = idx & 1023;
        int k = idx >> 10;                             // 0..31
        float s = g2[n] * rsqrtf(v2[n] + EPSV);
        g_Bh[n * 32 + k] = __float2half_rn(W2[k * 1024 + n] * s);
        if (k == 0) {
            g_b2f[n] = (b2[n] - m2[n]) * s + be2[n];
            if (n < 32) {
                float s1 = g1[n] * rsqrtf(v1[n] + EPSV);
                g_b1f[n] = (b1[n] - m1[n]) * s1 + be1[n];
                #pragma unroll
                for (int d = 0; d < 16; d++)
                    g_W1f[d * 32 + n] = W1[d * 32 + n] * s1;
            }
            if (n == 0) {
                int all0 = 1;
                for (int i = 0; i < 64; i++)
                    if (ei32[2 * i + 1] != 0) { all0 = 0; break; }
                g_is64 = all0;
            }
        }
        return;
    }

    __shared__ float root_s[1024];
    __shared__ float bias_s[32];
    int t = threadIdx.x;
    for (int i = t; i < 1024; i += 256) root_s[i] = root[i];
    if (t < 32) bias_s[t] = bias[t];
    __syncthreads();
    int lane = t & 31, w = t >> 5;
    int n = (blockIdx.x - FOLD_BLOCKS) * 8 + w;
    if (n >= NN) return;
    float xv = x[n * 32 + lane];
    float acc = bias_s[lane];
    #pragma unroll
    for (int i = 0; i < 32; i++)
        acc = fmaf(__shfl_sync(0xffffffffu, xv, i), root_s[i * 32 + lane], acc);
    out[n * 32 + lane] = acc;
}

// ---------------------------------------------------------------------------
// Persistent fused edge kernel: o-split warps, 2 CTAs/SM, fp16 mma.sync.
// Warp (Mw,Nw): rows Mw*32..+31, output cols o in [Nw*8, Nw*8+8), all 32 i.
// B rows per nb(=i): n = nb*32 + Nw*8 + row  -> each (edge,o) owned by ONE
// warp; msg = 8 floats/thread, single-copy MSG buffer, no cross-warp sum.
// ---------------------------------------------------------------------------
extern __shared__ char smem[];

__global__ void __launch_bounds__(512, 2)
edge_kernel(const float* __restrict__ x,
            const int*   __restrict__ ei32,
            const float* __restrict__ edge_attr,
            float* __restrict__ out)
{
    const int tid = threadIdx.x;
    const int lane = tid & 31, wid = tid >> 5;
    const int Mw = wid & 3, Nw = wid >> 2;              // 4 M-warps x 4 N-warps
    uint32_t su = smem_u32(smem);

    // ---- persistent copies: B, b2f, W1f, b1f ----
    {
        const int4* bs = (const int4*)g_Bh;
        for (int i = tid; i < 4096; i += 512) {        // 1024 rows x 4 int4
            int n = i >> 2, seg = i & 3;
            *(int4*)(smem + OFF_BS + n * BSTRIDE + seg * 16) = bs[i];
        }
        float* b2w = (float*)(smem + OFF_B2S);
        for (int i = tid; i < 1024; i += 512) b2w[i] = g_b2f[i];
        float* w1w = (float*)(smem + OFF_W1S);
        if (tid < 512) w1w[tid] = g_W1f[tid];
        if (tid < 32) ((float*)(smem + OFF_B1S))[tid] = g_b1f[tid];
    }
    const int is64 = g_is64;
    __syncthreads();

    // A ldsm: rows Mw*32 + (lane&15), k-half chunks
    uint32_t a_base = su + OFF_AS + (uint32_t)(Mw * 32 + (lane & 15)) * ASTRIDE + (lane >> 4) * 16;
    // B ldsm4 base: row (Nw*8 + lane&7), chunk lane>>3; per nb add nb*32*BSTRIDE
    uint32_t b_base = su + OFF_BS + (uint32_t)(Nw * 8 + (lane & 7)) * BSTRIDE + (lane >> 3) * 16;

    const float* b2s = (const float*)(smem + OFF_B2S);
    float* msf       = (float*)(smem + OFF_MSG);
    int* dst_s       = (int*)(smem + OFF_DST);

    const int e  = tid >> 2;      // edge within tile (4 threads per edge)
    const int qf = tid & 3;       // quarter: k-range [qf*8, qf*8+8)
    const int e3 = wid * 8 + (lane >> 2);   // phase-3 edge
    const int q3 = lane & 3;                // phase-3 o-quarter
    const int bcol = Nw * 8 + (lane & 3) * 2;   // o column pair within b2s row
    const int r0 = Mw * 32 + (lane >> 2);

    for (int tile = blockIdx.x; tile < NTILES; tile += EGRID) {
        // ============ phase 1: gather x_j (fp16), layer 1, A-tile ============
        {
            int eid = tile * 128 + e;
            int valid = eid < NE;
            int eidc = valid ? eid : NE - 1;
            int src, dd;
            if (is64) { src = ei32[2 * eidc]; dd = ei32[2 * (NE + eidc)]; }
            else      { src = ei32[eidc];     dd = ei32[NE + eidc]; }
            if (qf == 0) dst_s[e] = valid ? dd : -1;

            // x gather -> fp16 row-major [e][i] (16B-aligned: XSTRIDE=80)
            const float4* xr = (const float4*)(x + (size_t)src * 32) + qf * 2;
            float4 v0 = xr[0], v1 = xr[1];
            union { __half2 h[4]; uint4 u; } xu;
            xu.h[0] = __floats2half2_rn(v0.x, v0.y);
            xu.h[1] = __floats2half2_rn(v0.z, v0.w);
            xu.h[2] = __floats2half2_rn(v1.x, v1.y);
            xu.h[3] = __floats2half2_rn(v1.z, v1.w);
            *(uint4*)(smem + OFF_XJ + e * XSTRIDE + qf * 16) = xu.u;

            // edge_attr (sequential)
            const float4* er = (const float4*)(edge_attr + (size_t)eidc * 16);
            float4 q0 = er[0], q1 = er[1], q2 = er[2], q3v = er[3];
            float eav[16] = {q0.x,q0.y,q0.z,q0.w, q1.x,q1.y,q1.z,q1.w,
                             q2.x,q2.y,q2.z,q2.w, q3v.x,q3v.y,q3v.z,q3v.w};

            // layer 1: this thread's 8 k-values
            float hval[8];
            const float* W1s = (const float*)(smem + OFF_W1S) + qf * 8;
            const float* b1s = (const float*)(smem + OFF_B1S) + qf * 8;
            #pragma unroll
            for (int k = 0; k < 8; k++) hval[k] = b1s[k];
            #pragma unroll
            for (int d = 0; d < 16; d++) {
                float a = eav[d];
                #pragma unroll
                for (int k = 0; k < 8; k++)
                    hval[k] = fmaf(a, W1s[d * 32 + k], hval[k]);
            }
            #pragma unroll
            for (int k = 0; k < 8; k++) hval[k] = fmaxf(hval[k], SLOPE * hval[k]);

            union { __half2 h2[4]; uint4 u4; } pk;
            #pragma unroll
            for (int j = 0; j < 4; j++)
                pk.h2[j] = __halves2half2(__float2half_rn(hval[2 * j]),
                                          __float2half_rn(hval[2 * j + 1]));
            *(uint4*)(smem + OFF_AS + e * ASTRIDE + qf * 16) = pk.u4;
        }
        __syncthreads();

        // ============ phase 2: A-frags + MMA sweep over i ============
        uint32_t af[2][2][4];   // [row-chunk][k-half]
        #pragma unroll
        for (int c = 0; c < 2; c++) {
            ldsm4(af[c][0], a_base + c * (16 * ASTRIDE));
            ldsm4(af[c][1], a_base + c * (16 * ASTRIDE) + 32);
        }
        const int dd3 = dst_s[e3];

        float msg[4][2];
        #pragma unroll
        for (int r = 0; r < 4; r++) { msg[r][0] = 0.f; msg[r][1] = 0.f; }

        const uint32_t* xjh = (const uint32_t*)(smem + OFF_XJ);  // half2 words, row stride 20

        #pragma unroll 2
        for (int g = 0; g < 16; g++) {           // i-pairs: i = 2g, 2g+1
            uint32_t w0 = xjh[(r0)      * 20 + g];
            uint32_t w1 = xjh[(r0 + 8)  * 20 + g];
            uint32_t w2 = xjh[(r0 + 16) * 20 + g];
            uint32_t w3 = xjh[(r0 + 24) * 20 + g];
            float2 xf0 = __half22float2(*(const __half2*)&w0);
            float2 xf1 = __half22float2(*(const __half2*)&w1);
            float2 xf2 = __half22float2(*(const __half2*)&w2);
            float2 xf3 = __half22float2(*(const __half2*)&w3);

            #pragma unroll
            for (int j = 0; j < 2; j++) {
                int nb = 2 * g + j;              // i index
                uint32_t gg[4];
                ldsm4(gg, b_base + (uint32_t)nb * (32 * BSTRIDE));
                float2 b2v = *(const float2*)(b2s + nb * 32 + bcol);

                float c0[4] = {b2v.x, b2v.y, b2v.x, b2v.y};
                float c1[4] = {b2v.x, b2v.y, b2v.x, b2v.y};
                mma_f16(c0, af[0][0], gg);      mma_f16(c1, af[1][0], gg);
                mma_f16(c0, af[0][1], gg + 2);  mma_f16(c1, af[1][1], gg + 2);

                float x0 = j ? xf0.y : xf0.x;
                float x1 = j ? xf1.y : xf1.x;
                float x2 = j ? xf2.y : xf2.x;
                float x3 = j ? xf3.y : xf3.x;
                float v;
                v = fmaxf(c0[0], SLOPE * c0[0]); msg[0][0] = fmaf(x0, v, msg[0][0]);
                v = fmaxf(c0[1], SLOPE * c0[1]); msg[0][1] = fmaf(x0, v, msg[0][1]);
                v = fmaxf(c0[2], SLOPE * c0[2]); msg[1][0] = fmaf(x1, v, msg[1][0]);
                v = fmaxf(c0[3], SLOPE * c0[3]); msg[1][1] = fmaf(x1, v, msg[1][1]);
                v = fmaxf(c1[0], SLOPE * c1[0]); msg[2][0] = fmaf(x2, v, msg[2][0]);
                v = fmaxf(c1[1], SLOPE * c1[1]); msg[2][1] = fmaf(x2, v, msg[2][1]);
                v = fmaxf(c1[2], SLOPE * c1[2]); msg[3][0] = fmaf(x3, v, msg[3][0]);
                v = fmaxf(c1[3], SLOPE * c1[3]); msg[3][1] = fmaf(x3, v, msg[3][1]);
            }
        }
        __syncthreads();   // all A/XJ reads done before MSG overlays them

        // ============ phase 3: single-copy msg -> smem, red.v4 scatter ============
        #pragma unroll
        for (int r = 0; r < 4; r++)
            *(float2*)(msf + (size_t)(r0 + 8 * r) * MSTRIDE + bcol) =
                make_float2(msg[r][0], msg[r][1]);
        __syncthreads();

        if (dd3 >= 0) {
            const float* row = msf + e3 * MSTRIDE + q3 * 8;
            float4 s0 = *(const float4*)(row);
            float4 s1 = *(const float4*)(row + 4);
            float* gp = out + (size_t)dd3 * 32 + q3 * 8;
            red_v4(gp, s0);
            red_v4(gp + 4, s1);
        }
        __syncthreads();   // MSG reads done before next tile's A/XJ writes
    }
}

// ---------------------------------------------------------------------------
extern "C" void kernel_launch(void* const* d_in, const int* in_sizes, int n_in,
                              void* d_out, int out_size)
{
    const float* x    = (const float*)d_in[0];
    const int*   ei   = (const int*)d_in[1];
    const float* ea   = (const float*)d_in[2];
    const float* W1   = (const float*)d_in[4];
    const float* b1   = (const float*)d_in[5];
    const float* g1   = (const float*)d_in[6];
    const float* be1  = (const float*)d_in[7];
    const float* m1   = (const float*)d_in[8];
    const float* v1   = (const float*)d_in[9];
    const float* W2   = (const float*)d_in[10];
    const float* b2   = (const float*)d_in[11];
    const float* g2   = (const float*)d_in[12];
    const float* be2  = (const float*)d_in[13];
    const float* m2   = (const float*)d_in[14];
    const float* v2   = (const float*)d_in[15];
    const float* root = (const float*)d_in[16];
    const float* bias = (const float*)d_in[17];
    float* out = (float*)d_out;

    cudaFuncSetAttribute(edge_kernel, cudaFuncAttributeMaxDynamicSharedMemorySize, SMEM_BYTES);

    prep_kernel<<<FOLD_BLOCKS + INIT_BLOCKS, 256>>>(
        W1, b1, g1, be1, m1, v1, W2, b2, g2, be2, m2, v2, ei,
        x, root, bias, out);
    edge_kernel<<<EGRID, 512, SMEM_BYTES>>>(x, ei, ea, out);
}